// round 2
// baseline (speedup 1.0000x reference)
#include <cuda_runtime.h>
#include <cstdint>

#define NT 4096
#define DM 1024

// Scratch (static __device__ globals — allocation-free per harness rules)
__device__ float g_q[(size_t)NT * DM];
__device__ float g_k[(size_t)NT * DM];
__device__ float g_v[(size_t)NT * DM];
__device__ float g_s[(size_t)NT * NT];

// ---------------------------------------------------------------------------
// GEMM NT: C[M,N] = A[M,K] * B[N,K]^T   (both A and B are K-major row-major)
// 128x128 tile, BK=16, 256 threads, 8x8 per thread.
// CAUSAL: skip blocks entirely above the diagonal (bx > by).
// ---------------------------------------------------------------------------
template<bool CAUSAL>
__global__ __launch_bounds__(256)
void gemm_nt_kernel(const float* __restrict__ A, const float* __restrict__ B,
                    float* __restrict__ C, int M, int Ncols, int K)
{
    constexpr int BM = 128, BN = 128, BK = 16;
    __shared__ float As[BK][BM];
    __shared__ float Bs[BK][BN];

    const int bx = blockIdx.x, by = blockIdx.y;
    if (CAUSAL && bx > by) return;

    const int m0 = by * BM, n0 = bx * BN;
    const int t  = threadIdx.x;
    const int tx = t & 15, ty = t >> 4;

    float acc[8][8];
#pragma unroll
    for (int i = 0; i < 8; i++)
#pragma unroll
        for (int j = 0; j < 8; j++) acc[i][j] = 0.f;

    const float* Ap = A + (size_t)m0 * K;
    const float* Bp = B + (size_t)n0 * K;

    for (int k0 = 0; k0 < K; k0 += BK) {
        // 512 float4 per tile; 2 per thread
#pragma unroll
        for (int l = t; l < 512; l += 256) {
            const int r  = l >> 2;        // row within tile 0..127
            const int cg = l & 3;         // k-group 0..3 (4 floats each)
            float4 va = *reinterpret_cast<const float4*>(Ap + (size_t)r * K + k0 + cg * 4);
            As[cg * 4 + 0][r] = va.x; As[cg * 4 + 1][r] = va.y;
            As[cg * 4 + 2][r] = va.z; As[cg * 4 + 3][r] = va.w;
            float4 vb = *reinterpret_cast<const float4*>(Bp + (size_t)r * K + k0 + cg * 4);
            Bs[cg * 4 + 0][r] = vb.x; Bs[cg * 4 + 1][r] = vb.y;
            Bs[cg * 4 + 2][r] = vb.z; Bs[cg * 4 + 3][r] = vb.w;
        }
        __syncthreads();

#pragma unroll
        for (int k = 0; k < BK; k++) {
            float a[8], b[8];
            *reinterpret_cast<float4*>(&a[0]) = *reinterpret_cast<const float4*>(&As[k][ty * 8]);
            *reinterpret_cast<float4*>(&a[4]) = *reinterpret_cast<const float4*>(&As[k][ty * 8 + 4]);
            *reinterpret_cast<float4*>(&b[0]) = *reinterpret_cast<const float4*>(&Bs[k][tx * 8]);
            *reinterpret_cast<float4*>(&b[4]) = *reinterpret_cast<const float4*>(&Bs[k][tx * 8 + 4]);
#pragma unroll
            for (int i = 0; i < 8; i++)
#pragma unroll
                for (int j = 0; j < 8; j++) acc[i][j] += a[i] * b[j];
        }
        __syncthreads();
    }

#pragma unroll
    for (int i = 0; i < 8; i++) {
        float* crow = C + (size_t)(m0 + ty * 8 + i) * Ncols + n0 + tx * 8;
        float4 v0 = make_float4(acc[i][0], acc[i][1], acc[i][2], acc[i][3]);
        float4 v1 = make_float4(acc[i][4], acc[i][5], acc[i][6], acc[i][7]);
        *reinterpret_cast<float4*>(crow)     = v0;
        *reinterpret_cast<float4*>(crow + 4) = v1;
    }
}

// ---------------------------------------------------------------------------
// GEMM NN with causal k-limit: C[M,N] = A[M,K] * B[K,N], k < m0+BM only
// (weights above the diagonal are exact zeros, written by softmax kernel)
// ---------------------------------------------------------------------------
__global__ __launch_bounds__(256)
void gemm_nn_causal_kernel(const float* __restrict__ A, const float* __restrict__ B,
                           float* __restrict__ C, int M, int Ncols, int K)
{
    constexpr int BM = 128, BN = 128, BK = 16;
    __shared__ float As[BK][BM];
    __shared__ float Bs[BK][BN];

    const int bx = blockIdx.x, by = blockIdx.y;
    const int m0 = by * BM, n0 = bx * BN;
    const int t  = threadIdx.x;
    const int tx = t & 15, ty = t >> 4;

    float acc[8][8];
#pragma unroll
    for (int i = 0; i < 8; i++)
#pragma unroll
        for (int j = 0; j < 8; j++) acc[i][j] = 0.f;

    const float* Ap = A + (size_t)m0 * K;
    const int kmax = min(K, m0 + BM);   // causal: columns beyond row-tile are zero

    for (int k0 = 0; k0 < kmax; k0 += BK) {
#pragma unroll
        for (int l = t; l < 512; l += 256) {
            {   // A: rows m, contiguous k — store transposed
                const int r  = l >> 2;
                const int cg = l & 3;
                float4 va = *reinterpret_cast<const float4*>(Ap + (size_t)r * K + k0 + cg * 4);
                As[cg * 4 + 0][r] = va.x; As[cg * 4 + 1][r] = va.y;
                As[cg * 4 + 2][r] = va.z; As[cg * 4 + 3][r] = va.w;
            }
            {   // B: rows k, contiguous n — direct store
                const int kk = l >> 5;        // 0..15
                const int ng = l & 31;        // 0..31 (4 floats each)
                float4 vb = *reinterpret_cast<const float4*>(B + (size_t)(k0 + kk) * Ncols + n0 + ng * 4);
                *reinterpret_cast<float4*>(&Bs[kk][ng * 4]) = vb;
            }
        }
        __syncthreads();

#pragma unroll
        for (int k = 0; k < BK; k++) {
            float a[8], b[8];
            *reinterpret_cast<float4*>(&a[0]) = *reinterpret_cast<const float4*>(&As[k][ty * 8]);
            *reinterpret_cast<float4*>(&a[4]) = *reinterpret_cast<const float4*>(&As[k][ty * 8 + 4]);
            *reinterpret_cast<float4*>(&b[0]) = *reinterpret_cast<const float4*>(&Bs[k][tx * 8]);
            *reinterpret_cast<float4*>(&b[4]) = *reinterpret_cast<const float4*>(&Bs[k][tx * 8 + 4]);
#pragma unroll
            for (int i = 0; i < 8; i++)
#pragma unroll
                for (int j = 0; j < 8; j++) acc[i][j] += a[i] * b[j];
        }
        __syncthreads();
    }

#pragma unroll
    for (int i = 0; i < 8; i++) {
        float* crow = C + (size_t)(m0 + ty * 8 + i) * Ncols + n0 + tx * 8;
        float4 v0 = make_float4(acc[i][0], acc[i][1], acc[i][2], acc[i][3]);
        float4 v1 = make_float4(acc[i][4], acc[i][5], acc[i][6], acc[i][7]);
        *reinterpret_cast<float4*>(crow)     = v0;
        *reinterpret_cast<float4*>(crow + 4) = v1;
    }
}

// ---------------------------------------------------------------------------
// Exact JAX *partitionable* threefry2x32 uniform (key = (0, 42)).
// Recent JAX (jax_threefry_partitionable=True, default since 0.4.36):
//   counter for flat index i (uint64): words (hi, lo) = (i >> 32, i & 0xffffffff)
//   (x0, x1) = threefry2x32(key, (hi, lo));  bits32 = x0 ^ x1
//   u = bitcast((bits >> 9) | 0x3f800000) - 1 ;  keep = u < 0.9f
// Here i < 2^24 so hi = 0.
// ---------------------------------------------------------------------------
__device__ __forceinline__ float jax_uniform(uint32_t idx)
{
    const uint32_t k0 = 0u, k1 = 42u;
    const uint32_t k2 = 0x1BD11BDAu ^ k0 ^ k1;

    uint32_t x0 = 0u  + k0;   // hi counter word = 0
    uint32_t x1 = idx + k1;   // lo counter word = flat index

#define TF_ROUND(r) { x0 += x1; x1 = __funnelshift_l(x1, x1, (r)); x1 ^= x0; }
    TF_ROUND(13) TF_ROUND(15) TF_ROUND(26) TF_ROUND(6)
    x0 += k1; x1 += k2 + 1u;
    TF_ROUND(17) TF_ROUND(29) TF_ROUND(16) TF_ROUND(24)
    x0 += k2; x1 += k0 + 2u;
    TF_ROUND(13) TF_ROUND(15) TF_ROUND(26) TF_ROUND(6)
    x0 += k0; x1 += k1 + 3u;
    TF_ROUND(17) TF_ROUND(29) TF_ROUND(16) TF_ROUND(24)
    x0 += k1; x1 += k2 + 4u;
    TF_ROUND(13) TF_ROUND(15) TF_ROUND(26) TF_ROUND(6)
    x0 += k2; x1 += k0 + 5u;
#undef TF_ROUND

    uint32_t bits = x0 ^ x1;   // 32-bit partitionable combine
    return __uint_as_float((bits >> 9) | 0x3f800000u) - 1.0f;
}

// ---------------------------------------------------------------------------
// Row softmax (causal, scale 1/32) + JAX dropout, in place on g_s.
// One block of 256 threads per row. Writes full row (zeros above diagonal).
// ---------------------------------------------------------------------------
__global__ __launch_bounds__(256)
void softmax_dropout_kernel(float* __restrict__ S)
{
    const int i = blockIdx.x;
    const int t = threadIdx.x;
    const int len = i + 1;
    float* row = S + (size_t)i * NT;
    __shared__ float red[256];

    const float inv_scale = 0.03125f;  // 1/sqrt(1024)

    // pass 1: max over j <= i
    float lm = -INFINITY;
    for (int j = t; j < len; j += 256) lm = fmaxf(lm, row[j] * inv_scale);
    red[t] = lm; __syncthreads();
    for (int o = 128; o > 0; o >>= 1) {
        if (t < o) red[t] = fmaxf(red[t], red[t + o]);
        __syncthreads();
    }
    const float m = red[0];
    __syncthreads();

    // pass 2: exp + sum, store exp in place
    float ls = 0.f;
    for (int j = t; j < len; j += 256) {
        float e = __expf(row[j] * inv_scale - m);
        row[j] = e;
        ls += e;
    }
    red[t] = ls; __syncthreads();
    for (int o = 128; o > 0; o >>= 1) {
        if (t < o) red[t] += red[t + o];
        __syncthreads();
    }
    const float inv_sum = 1.0f / red[0];
    const float keep_scale = inv_sum * (1.0f / 0.9f);

    // pass 3: dropout + normalize; zero above diagonal
    const uint32_t base = (uint32_t)i * (uint32_t)NT;
    for (int j = t; j < NT; j += 256) {
        float w = 0.f;
        if (j < len) {
            float u = jax_uniform(base + (uint32_t)j);
            w = (u < 0.9f) ? row[j] * keep_scale : 0.f;
        }
        row[j] = w;
    }
}

// ---------------------------------------------------------------------------
extern "C" void kernel_launch(void* const* d_in, const int* in_sizes, int n_in,
                              void* d_out, int out_size)
{
    const float* x  = (const float*)d_in[0];
    const float* wq = (const float*)d_in[1];
    const float* wk = (const float*)d_in[2];
    const float* wv = (const float*)d_in[3];
    float* out = (float*)d_out;

    float *q, *k, *v, *s;
    cudaGetSymbolAddress((void**)&q, g_q);
    cudaGetSymbolAddress((void**)&k, g_k);
    cudaGetSymbolAddress((void**)&v, g_v);
    cudaGetSymbolAddress((void**)&s, g_s);

    dim3 blk(256);

    // QKV projections: C[N, D] = x[N, D] @ w[D, D]^T
    dim3 grid_qkv(DM / 128, NT / 128);
    gemm_nt_kernel<false><<<grid_qkv, blk>>>(x, wq, q, NT, DM, DM);
    gemm_nt_kernel<false><<<grid_qkv, blk>>>(x, wk, k, NT, DM, DM);
    gemm_nt_kernel<false><<<grid_qkv, blk>>>(x, wv, v, NT, DM, DM);

    // scores = Q @ K^T  (lower-triangular blocks only)
    dim3 grid_s(NT / 128, NT / 128);
    gemm_nt_kernel<true><<<grid_s, blk>>>(q, k, s, NT, NT, DM);

    // softmax(/32, causal) + exact-JAX dropout, in place
    softmax_dropout_kernel<<<NT, blk>>>(s);

    // out = weights @ V (causal k-limit per row tile)
    dim3 grid_o(DM / 128, NT / 128);
    gemm_nn_causal_kernel<<<grid_o, blk>>>(s, v, out, NT, DM, NT);
}

// round 4
// speedup vs baseline: 1.9371x; 1.9371x over previous
#include <cuda_runtime.h>
#include <cstdint>

#define NT 4096
#define DM 1024

// Scratch (static __device__ globals — allocation-free per harness rules)
__device__ float g_q[(size_t)NT * DM];
__device__ float g_k[(size_t)NT * DM];
__device__ float g_v[(size_t)NT * DM];
__device__ float g_s[(size_t)NT * NT];

__device__ __forceinline__ uint32_t f2tf32(float x)
{
    uint32_t y;
    asm("cvt.rna.tf32.f32 %0, %1;" : "=r"(y) : "f"(x));
    return y;
}

__device__ __forceinline__ void mma_tf32(float c[4], uint32_t a0, uint32_t a1,
                                         uint32_t a2, uint32_t a3,
                                         uint32_t b0, uint32_t b1)
{
    asm volatile(
        "mma.sync.aligned.m16n8k8.row.col.f32.tf32.tf32.f32 "
        "{%0,%1,%2,%3}, {%4,%5,%6,%7}, {%8,%9}, {%0,%1,%2,%3};"
        : "+f"(c[0]), "+f"(c[1]), "+f"(c[2]), "+f"(c[3])
        : "r"(a0), "r"(a1), "r"(a2), "r"(a3), "r"(b0), "r"(b1));
}

// ---------------------------------------------------------------------------
// tf32 MMA GEMM NT: C[M,N] = A[M,K] * B[N,K]^T   (A, B k-major)
// 128x128 tile, BK=32, 256 threads (8 warps: 2 m-slabs x 4 n-slabs of 64x32).
// CAUSAL: skip blocks strictly above the diagonal.
// ---------------------------------------------------------------------------
template<bool CAUSAL>
__global__ __launch_bounds__(256)
void mma_nt_kernel(const float* __restrict__ A, const float* __restrict__ B,
                   float* __restrict__ C, int M, int Ncols, int K)
{
    constexpr int BM = 128, BN = 128, BK = 32;
    constexpr int LDS = BM + 8;                 // stride 136 ≡ 8 mod 32: conflict-free
    __shared__ uint32_t As[BK][LDS];
    __shared__ uint32_t Bs[BK][LDS];

    const int bx = blockIdx.x, by = blockIdx.y;
    if (CAUSAL && bx > by) return;

    const int m0 = by * BM, n0 = bx * BN;
    const int t    = threadIdx.x;
    const int lane = t & 31, warp = t >> 5;
    const int wm = warp & 1, wn = warp >> 1;    // 2 x 4 warp grid
    const int gID = lane >> 2, tig = lane & 3;

    float c[4][4][4];
#pragma unroll
    for (int i = 0; i < 4; i++)
#pragma unroll
        for (int j = 0; j < 4; j++)
#pragma unroll
            for (int r = 0; r < 4; r++) c[i][j][r] = 0.f;

    const float* Ap = A + (size_t)m0 * K;
    const float* Bp = B + (size_t)n0 * K;

    for (int k0 = 0; k0 < K; k0 += BK) {
        // each operand tile: 128 rows x 32 k = 1024 float4; 4 per thread
#pragma unroll
        for (int l = t; l < 1024; l += 256) {
            const int r  = l >> 3;       // tile row 0..127
            const int cg = l & 7;        // k-group (4 floats)
            float4 va = *reinterpret_cast<const float4*>(Ap + (size_t)r * K + k0 + cg * 4);
            As[cg * 4 + 0][r] = f2tf32(va.x); As[cg * 4 + 1][r] = f2tf32(va.y);
            As[cg * 4 + 2][r] = f2tf32(va.z); As[cg * 4 + 3][r] = f2tf32(va.w);
            float4 vb = *reinterpret_cast<const float4*>(Bp + (size_t)r * K + k0 + cg * 4);
            Bs[cg * 4 + 0][r] = f2tf32(vb.x); Bs[cg * 4 + 1][r] = f2tf32(vb.y);
            Bs[cg * 4 + 2][r] = f2tf32(vb.z); Bs[cg * 4 + 3][r] = f2tf32(vb.w);
        }
        __syncthreads();

#pragma unroll
        for (int ks = 0; ks < 4; ks++) {
            const int kr = ks * 8;
            uint32_t a[4][4], b[4][2];
#pragma unroll
            for (int mt = 0; mt < 4; mt++) {
                const int r0 = wm * 64 + mt * 16 + gID;
                a[mt][0] = As[kr + tig][r0];
                a[mt][1] = As[kr + tig][r0 + 8];
                a[mt][2] = As[kr + tig + 4][r0];
                a[mt][3] = As[kr + tig + 4][r0 + 8];
            }
#pragma unroll
            for (int nt = 0; nt < 4; nt++) {
                const int c0 = wn * 32 + nt * 8 + gID;
                b[nt][0] = Bs[kr + tig][c0];
                b[nt][1] = Bs[kr + tig + 4][c0];
            }
#pragma unroll
            for (int mt = 0; mt < 4; mt++)
#pragma unroll
                for (int nt = 0; nt < 4; nt++)
                    mma_tf32(c[mt][nt], a[mt][0], a[mt][1], a[mt][2], a[mt][3],
                             b[nt][0], b[nt][1]);
        }
        __syncthreads();
    }

#pragma unroll
    for (int mt = 0; mt < 4; mt++) {
        const int row = m0 + wm * 64 + mt * 16 + gID;
#pragma unroll
        for (int nt = 0; nt < 4; nt++) {
            const int col = n0 + wn * 32 + nt * 8 + tig * 2;
            *reinterpret_cast<float2*>(C + (size_t)row * Ncols + col) =
                make_float2(c[mt][nt][0], c[mt][nt][1]);
            *reinterpret_cast<float2*>(C + (size_t)(row + 8) * Ncols + col) =
                make_float2(c[mt][nt][2], c[mt][nt][3]);
        }
    }
}

// ---------------------------------------------------------------------------
// tf32 MMA GEMM NN with causal k-limit: C[M,N] = A[M,K] * B[K,N], k < m0+BM
// ---------------------------------------------------------------------------
__global__ __launch_bounds__(256)
void mma_nn_causal_kernel(const float* __restrict__ A, const float* __restrict__ B,
                          float* __restrict__ C, int M, int Ncols, int K)
{
    constexpr int BM = 128, BN = 128, BK = 32;
    constexpr int LDS = BM + 8;
    __shared__ uint32_t As[BK][LDS];
    __shared__ uint32_t Bs[BK][LDS];

    const int bx = blockIdx.x, by = blockIdx.y;
    const int m0 = by * BM, n0 = bx * BN;
    const int t    = threadIdx.x;
    const int lane = t & 31, warp = t >> 5;
    const int wm = warp & 1, wn = warp >> 1;
    const int gID = lane >> 2, tig = lane & 3;

    float c[4][4][4];
#pragma unroll
    for (int i = 0; i < 4; i++)
#pragma unroll
        for (int j = 0; j < 4; j++)
#pragma unroll
            for (int r = 0; r < 4; r++) c[i][j][r] = 0.f;

    const float* Ap = A + (size_t)m0 * K;
    const int kmax = min(K, m0 + BM);   // weights beyond row-tile are exact zeros

    for (int k0 = 0; k0 < kmax; k0 += BK) {
#pragma unroll
        for (int l = t; l < 1024; l += 256) {
            {   // A: rows m, contiguous k — store transposed [k][m]
                const int r  = l >> 3;
                const int cg = l & 7;
                float4 va = *reinterpret_cast<const float4*>(Ap + (size_t)r * K + k0 + cg * 4);
                As[cg * 4 + 0][r] = f2tf32(va.x); As[cg * 4 + 1][r] = f2tf32(va.y);
                As[cg * 4 + 2][r] = f2tf32(va.z); As[cg * 4 + 3][r] = f2tf32(va.w);
            }
            {   // B: rows k, contiguous n — direct store [k][n]
                const int kk = l >> 5;       // 0..31
                const int ng = l & 31;       // 0..31 (4 floats each)
                float4 vb = *reinterpret_cast<const float4*>(B + (size_t)(k0 + kk) * Ncols + n0 + ng * 4);
                Bs[kk][ng * 4 + 0] = f2tf32(vb.x); Bs[kk][ng * 4 + 1] = f2tf32(vb.y);
                Bs[kk][ng * 4 + 2] = f2tf32(vb.z); Bs[kk][ng * 4 + 3] = f2tf32(vb.w);
            }
        }
        __syncthreads();

#pragma unroll
        for (int ks = 0; ks < 4; ks++) {
            const int kr = ks * 8;
            uint32_t a[4][4], b[4][2];
#pragma unroll
            for (int mt = 0; mt < 4; mt++) {
                const int r0 = wm * 64 + mt * 16 + gID;
                a[mt][0] = As[kr + tig][r0];
                a[mt][1] = As[kr + tig][r0 + 8];
                a[mt][2] = As[kr + tig + 4][r0];
                a[mt][3] = As[kr + tig + 4][r0 + 8];
            }
#pragma unroll
            for (int nt = 0; nt < 4; nt++) {
                const int c0 = wn * 32 + nt * 8 + gID;
                b[nt][0] = Bs[kr + tig][c0];
                b[nt][1] = Bs[kr + tig + 4][c0];
            }
#pragma unroll
            for (int mt = 0; mt < 4; mt++)
#pragma unroll
                for (int nt = 0; nt < 4; nt++)
                    mma_tf32(c[mt][nt], a[mt][0], a[mt][1], a[mt][2], a[mt][3],
                             b[nt][0], b[nt][1]);
        }
        __syncthreads();
    }

#pragma unroll
    for (int mt = 0; mt < 4; mt++) {
        const int row = m0 + wm * 64 + mt * 16 + gID;
#pragma unroll
        for (int nt = 0; nt < 4; nt++) {
            const int col = n0 + wn * 32 + nt * 8 + tig * 2;
            *reinterpret_cast<float2*>(C + (size_t)row * Ncols + col) =
                make_float2(c[mt][nt][0], c[mt][nt][1]);
            *reinterpret_cast<float2*>(C + (size_t)(row + 8) * Ncols + col) =
                make_float2(c[mt][nt][2], c[mt][nt][3]);
        }
    }
}

// ---------------------------------------------------------------------------
// Exact JAX *partitionable* threefry2x32 uniform (key = (0, 42)).
//   (x0, x1) = threefry2x32((0,42), (0, i));  bits = x0 ^ x1
//   u = bitcast((bits >> 9) | 0x3f800000) - 1 ;  keep = u < 0.9f
// ---------------------------------------------------------------------------
__device__ __forceinline__ float jax_uniform(uint32_t idx)
{
    const uint32_t k0 = 0u, k1 = 42u;
    const uint32_t k2 = 0x1BD11BDAu ^ k0 ^ k1;

    uint32_t x0 = 0u  + k0;   // hi counter word = 0
    uint32_t x1 = idx + k1;   // lo counter word = flat index

#define TF_ROUND(r) { x0 += x1; x1 = __funnelshift_l(x1, x1, (r)); x1 ^= x0; }
    TF_ROUND(13) TF_ROUND(15) TF_ROUND(26) TF_ROUND(6)
    x0 += k1; x1 += k2 + 1u;
    TF_ROUND(17) TF_ROUND(29) TF_ROUND(16) TF_ROUND(24)
    x0 += k2; x1 += k0 + 2u;
    TF_ROUND(13) TF_ROUND(15) TF_ROUND(26) TF_ROUND(6)
    x0 += k0; x1 += k1 + 3u;
    TF_ROUND(17) TF_ROUND(29) TF_ROUND(16) TF_ROUND(24)
    x0 += k1; x1 += k2 + 4u;
    TF_ROUND(13) TF_ROUND(15) TF_ROUND(26) TF_ROUND(6)
    x0 += k2; x1 += k0 + 5u;
#undef TF_ROUND

    uint32_t bits = x0 ^ x1;
    return __uint_as_float((bits >> 9) | 0x3f800000u) - 1.0f;
}

// ---------------------------------------------------------------------------
// Row softmax (causal, scale 1/32) + JAX dropout, in place on g_s.
// ---------------------------------------------------------------------------
__global__ __launch_bounds__(256)
void softmax_dropout_kernel(float* __restrict__ S)
{
    const int i = blockIdx.x;
    const int t = threadIdx.x;
    const int len = i + 1;
    float* row = S + (size_t)i * NT;
    __shared__ float red[256];

    const float inv_scale = 0.03125f;  // 1/sqrt(1024)

    float lm = -INFINITY;
    for (int j = t; j < len; j += 256) lm = fmaxf(lm, row[j] * inv_scale);
    red[t] = lm; __syncthreads();
    for (int o = 128; o > 0; o >>= 1) {
        if (t < o) red[t] = fmaxf(red[t], red[t + o]);
        __syncthreads();
    }
    const float m = red[0];
    __syncthreads();

    float ls = 0.f;
    for (int j = t; j < len; j += 256) {
        float e = __expf(row[j] * inv_scale - m);
        row[j] = e;
        ls += e;
    }
    red[t] = ls; __syncthreads();
    for (int o = 128; o > 0; o >>= 1) {
        if (t < o) red[t] += red[t + o];
        __syncthreads();
    }
    const float inv_sum = 1.0f / red[0];
    const float keep_scale = inv_sum * (1.0f / 0.9f);

    const uint32_t base = (uint32_t)i * (uint32_t)NT;
    for (int j = t; j < NT; j += 256) {
        float w = 0.f;
        if (j < len) {
            float u = jax_uniform(base + (uint32_t)j);
            w = (u < 0.9f) ? row[j] * keep_scale : 0.f;
        }
        row[j] = w;
    }
}

// ---------------------------------------------------------------------------
extern "C" void kernel_launch(void* const* d_in, const int* in_sizes, int n_in,
                              void* d_out, int out_size)
{
    const float* x  = (const float*)d_in[0];
    const float* wq = (const float*)d_in[1];
    const float* wk = (const float*)d_in[2];
    const float* wv = (const float*)d_in[3];
    float* out = (float*)d_out;

    float *q, *k, *v, *s;
    cudaGetSymbolAddress((void**)&q, g_q);
    cudaGetSymbolAddress((void**)&k, g_k);
    cudaGetSymbolAddress((void**)&v, g_v);
    cudaGetSymbolAddress((void**)&s, g_s);

    dim3 blk(256);

    dim3 grid_qkv(DM / 128, NT / 128);
    mma_nt_kernel<false><<<grid_qkv, blk>>>(x, wq, q, NT, DM, DM);
    mma_nt_kernel<false><<<grid_qkv, blk>>>(x, wk, k, NT, DM, DM);
    mma_nt_kernel<false><<<grid_qkv, blk>>>(x, wv, v, NT, DM, DM);

    dim3 grid_s(NT / 128, NT / 128);
    mma_nt_kernel<true><<<grid_s, blk>>>(q, k, s, NT, NT, DM);

    softmax_dropout_kernel<<<NT, blk>>>(s);

    dim3 grid_o(DM / 128, NT / 128);
    mma_nn_causal_kernel<<<grid_o, blk>>>(s, v, out, NT, DM, NT);
}

// round 5
// speedup vs baseline: 2.9005x; 1.4974x over previous
#include <cuda_runtime.h>
#include <cstdint>

#define NT 4096
#define DM 1024

// Scratch (static __device__ globals — allocation-free per harness rules)
__device__ float g_q[(size_t)NT * DM];
__device__ float g_k[(size_t)NT * DM];
__device__ float g_v[(size_t)NT * DM];
__device__ float g_s[(size_t)NT * NT];

__device__ __forceinline__ uint32_t f2tf32(float x)
{
    uint32_t y;
    asm("cvt.rna.tf32.f32 %0, %1;" : "=r"(y) : "f"(x));
    return y;
}

__device__ __forceinline__ void mma_tf32(float c[4], uint32_t a0, uint32_t a1,
                                         uint32_t a2, uint32_t a3,
                                         uint32_t b0, uint32_t b1)
{
    asm volatile(
        "mma.sync.aligned.m16n8k8.row.col.f32.tf32.tf32.f32 "
        "{%0,%1,%2,%3}, {%4,%5,%6,%7}, {%8,%9}, {%0,%1,%2,%3};"
        : "+f"(c[0]), "+f"(c[1]), "+f"(c[2]), "+f"(c[3])
        : "r"(a0), "r"(a1), "r"(a2), "r"(a3), "r"(b0), "r"(b1));
}

__device__ __forceinline__ void cp_async16(uint32_t dst_smem, const void* src)
{
    asm volatile("cp.async.cg.shared.global [%0], [%1], 16;\n"
                 :: "r"(dst_smem), "l"(src));
}
__device__ __forceinline__ void cp_commit()
{
    asm volatile("cp.async.commit_group;\n" ::: "memory");
}
__device__ __forceinline__ void cp_wait0()
{
    asm volatile("cp.async.wait_group 0;\n" ::: "memory");
}

// ---------------------------------------------------------------------------
// tf32 MMA GEMM NT, cp.async double-buffered.
// C[M,N] = A[M,K] * B[N,K]^T. 128x128 tile, BK=32, 256 threads,
// 8 warps (2m x 4n of 64x32). Smem raw f32, [row][k] stride 36 (conflict-free).
// CAUSAL: skip blocks strictly above the diagonal.
// ---------------------------------------------------------------------------
template<bool CAUSAL>
__global__ __launch_bounds__(256, 2)
void mma_nt_kernel(const float* __restrict__ A, const float* __restrict__ B,
                   float* __restrict__ C, int M, int Ncols, int K)
{
    constexpr int BM = 128, BN = 128, BK = 32;
    constexpr int STR = BK + 4;                 // 36: 4*gID+tig banks, conflict-free
    constexpr int TSZ = BM * STR;               // floats per buffer

    extern __shared__ float sm[];
    float* As = sm;                 // [2][128][36]
    float* Bs = sm + 2 * TSZ;       // [2][128][36]

    const int bx = blockIdx.x, by = blockIdx.y;
    if (CAUSAL && bx > by) return;

    const int m0 = by * BM, n0 = bx * BN;
    const int t    = threadIdx.x;
    const int lane = t & 31, warp = t >> 5;
    const int wm = warp & 1, wn = warp >> 1;
    const int gID = lane >> 2, tig = lane & 3;

    const float* Ap = A + (size_t)m0 * K;
    const float* Bp = B + (size_t)n0 * K;

    const uint32_t sA = (uint32_t)__cvta_generic_to_shared(As);
    const uint32_t sB = (uint32_t)__cvta_generic_to_shared(Bs);

    float c[4][4][4];
#pragma unroll
    for (int i = 0; i < 4; i++)
#pragma unroll
        for (int j = 0; j < 4; j++)
#pragma unroll
            for (int r = 0; r < 4; r++) c[i][j][r] = 0.f;

    // issue one BK tile of A and B into buffer `buf`
    auto issue = [&](int k0, int buf) {
#pragma unroll
        for (int l = t; l < 1024; l += 256) {
            const int r  = l >> 3;      // tile row 0..127
            const int cg = l & 7;       // 16B chunk within row
            cp_async16(sA + (uint32_t)((buf * TSZ + r * STR + cg * 4) * 4),
                       Ap + (size_t)r * K + k0 + cg * 4);
            cp_async16(sB + (uint32_t)((buf * TSZ + r * STR + cg * 4) * 4),
                       Bp + (size_t)r * K + k0 + cg * 4);
        }
    };

    const int nk = K / BK;

    issue(0, 0);
    cp_commit();
    cp_wait0();
    __syncthreads();

    for (int i = 0; i < nk; i++) {
        const int buf = i & 1;
        if (i + 1 < nk) {
            issue((i + 1) * BK, buf ^ 1);
            cp_commit();
        }

        const float* A0 = As + buf * TSZ;
        const float* B0 = Bs + buf * TSZ;
#pragma unroll
        for (int ks = 0; ks < 4; ks++) {
            const int kr = ks * 8;
            uint32_t a[4][4], b[4][2];
#pragma unroll
            for (int mt = 0; mt < 4; mt++) {
                const int r0 = wm * 64 + mt * 16 + gID;
                a[mt][0] = f2tf32(A0[r0 * STR + kr + tig]);
                a[mt][1] = f2tf32(A0[(r0 + 8) * STR + kr + tig]);
                a[mt][2] = f2tf32(A0[r0 * STR + kr + tig + 4]);
                a[mt][3] = f2tf32(A0[(r0 + 8) * STR + kr + tig + 4]);
            }
#pragma unroll
            for (int nt = 0; nt < 4; nt++) {
                const int c0 = wn * 32 + nt * 8 + gID;
                b[nt][0] = f2tf32(B0[c0 * STR + kr + tig]);
                b[nt][1] = f2tf32(B0[c0 * STR + kr + tig + 4]);
            }
#pragma unroll
            for (int mt = 0; mt < 4; mt++)
#pragma unroll
                for (int nt = 0; nt < 4; nt++)
                    mma_tf32(c[mt][nt], a[mt][0], a[mt][1], a[mt][2], a[mt][3],
                             b[nt][0], b[nt][1]);
        }

        if (i + 1 < nk) cp_wait0();
        __syncthreads();
    }

#pragma unroll
    for (int mt = 0; mt < 4; mt++) {
        const int row = m0 + wm * 64 + mt * 16 + gID;
#pragma unroll
        for (int nt = 0; nt < 4; nt++) {
            const int col = n0 + wn * 32 + nt * 8 + tig * 2;
            *reinterpret_cast<float2*>(C + (size_t)row * Ncols + col) =
                make_float2(c[mt][nt][0], c[mt][nt][1]);
            *reinterpret_cast<float2*>(C + (size_t)(row + 8) * Ncols + col) =
                make_float2(c[mt][nt][2], c[mt][nt][3]);
        }
    }
}

// ---------------------------------------------------------------------------
// tf32 MMA GEMM NN with causal k-limit, cp.async double-buffered.
// C[M,N] = A[M,K] * B[K,N], k < m0+BM. A smem [m][k] stride 36;
// B smem [k][n] stride 136 (8*tig+gID banks, conflict-free).
// ---------------------------------------------------------------------------
__global__ __launch_bounds__(256, 2)
void mma_nn_causal_kernel(const float* __restrict__ A, const float* __restrict__ B,
                          float* __restrict__ C, int M, int Ncols, int K)
{
    constexpr int BM = 128, BN = 128, BK = 32;
    constexpr int STRA = BK + 4;                 // 36
    constexpr int STRB = BN + 8;                 // 136
    constexpr int TA = BM * STRA;                // 4608 floats
    constexpr int TB = BK * STRB;                // 4352 floats

    extern __shared__ float sm[];
    float* As = sm;                  // [2][128][36]
    float* Bs = sm + 2 * TA;         // [2][32][136]

    const int bx = blockIdx.x, by = blockIdx.y;
    const int m0 = by * BM, n0 = bx * BN;
    const int t    = threadIdx.x;
    const int lane = t & 31, warp = t >> 5;
    const int wm = warp & 1, wn = warp >> 1;
    const int gID = lane >> 2, tig = lane & 3;

    const float* Ap = A + (size_t)m0 * K;
    const uint32_t sA = (uint32_t)__cvta_generic_to_shared(As);
    const uint32_t sB = (uint32_t)__cvta_generic_to_shared(Bs);

    float c[4][4][4];
#pragma unroll
    for (int i = 0; i < 4; i++)
#pragma unroll
        for (int j = 0; j < 4; j++)
#pragma unroll
            for (int r = 0; r < 4; r++) c[i][j][r] = 0.f;

    auto issue = [&](int k0, int buf) {
#pragma unroll
        for (int l = t; l < 1024; l += 256) {
            {   // A tile: 128 rows x 32 k
                const int r  = l >> 3;
                const int cg = l & 7;
                cp_async16(sA + (uint32_t)((buf * TA + r * STRA + cg * 4) * 4),
                           Ap + (size_t)r * K + k0 + cg * 4);
            }
            {   // B tile: 32 rows(k) x 128 cols(n)
                const int kk = l >> 5;
                const int ng = l & 31;
                cp_async16(sB + (uint32_t)((buf * TB + kk * STRB + ng * 4) * 4),
                           B + (size_t)(k0 + kk) * Ncols + n0 + ng * 4);
            }
        }
    };

    const int kmax = min(K, m0 + BM);   // weights beyond row-tile are exact zeros
    const int nk = kmax / BK;

    issue(0, 0);
    cp_commit();
    cp_wait0();
    __syncthreads();

    for (int i = 0; i < nk; i++) {
        const int buf = i & 1;
        if (i + 1 < nk) {
            issue((i + 1) * BK, buf ^ 1);
            cp_commit();
        }

        const float* A0 = As + buf * TA;
        const float* B0 = Bs + buf * TB;
#pragma unroll
        for (int ks = 0; ks < 4; ks++) {
            const int kr = ks * 8;
            uint32_t a[4][4], b[4][2];
#pragma unroll
            for (int mt = 0; mt < 4; mt++) {
                const int r0 = wm * 64 + mt * 16 + gID;
                a[mt][0] = f2tf32(A0[r0 * STRA + kr + tig]);
                a[mt][1] = f2tf32(A0[(r0 + 8) * STRA + kr + tig]);
                a[mt][2] = f2tf32(A0[r0 * STRA + kr + tig + 4]);
                a[mt][3] = f2tf32(A0[(r0 + 8) * STRA + kr + tig + 4]);
            }
#pragma unroll
            for (int nt = 0; nt < 4; nt++) {
                const int c0 = wn * 32 + nt * 8 + gID;
                b[nt][0] = f2tf32(B0[(kr + tig) * STRB + c0]);
                b[nt][1] = f2tf32(B0[(kr + tig + 4) * STRB + c0]);
            }
#pragma unroll
            for (int mt = 0; mt < 4; mt++)
#pragma unroll
                for (int nt = 0; nt < 4; nt++)
                    mma_tf32(c[mt][nt], a[mt][0], a[mt][1], a[mt][2], a[mt][3],
                             b[nt][0], b[nt][1]);
        }

        if (i + 1 < nk) cp_wait0();
        __syncthreads();
    }

#pragma unroll
    for (int mt = 0; mt < 4; mt++) {
        const int row = m0 + wm * 64 + mt * 16 + gID;
#pragma unroll
        for (int nt = 0; nt < 4; nt++) {
            const int col = n0 + wn * 32 + nt * 8 + tig * 2;
            *reinterpret_cast<float2*>(C + (size_t)row * Ncols + col) =
                make_float2(c[mt][nt][0], c[mt][nt][1]);
            *reinterpret_cast<float2*>(C + (size_t)(row + 8) * Ncols + col) =
                make_float2(c[mt][nt][2], c[mt][nt][3]);
        }
    }
}

// ---------------------------------------------------------------------------
// Exact JAX *partitionable* threefry2x32 uniform (key = (0, 42)).
// ---------------------------------------------------------------------------
__device__ __forceinline__ float jax_uniform(uint32_t idx)
{
    const uint32_t k0 = 0u, k1 = 42u;
    const uint32_t k2 = 0x1BD11BDAu ^ k0 ^ k1;

    uint32_t x0 = 0u  + k0;
    uint32_t x1 = idx + k1;

#define TF_ROUND(r) { x0 += x1; x1 = __funnelshift_l(x1, x1, (r)); x1 ^= x0; }
    TF_ROUND(13) TF_ROUND(15) TF_ROUND(26) TF_ROUND(6)
    x0 += k1; x1 += k2 + 1u;
    TF_ROUND(17) TF_ROUND(29) TF_ROUND(16) TF_ROUND(24)
    x0 += k2; x1 += k0 + 2u;
    TF_ROUND(13) TF_ROUND(15) TF_ROUND(26) TF_ROUND(6)
    x0 += k0; x1 += k1 + 3u;
    TF_ROUND(17) TF_ROUND(29) TF_ROUND(16) TF_ROUND(24)
    x0 += k1; x1 += k2 + 4u;
    TF_ROUND(13) TF_ROUND(15) TF_ROUND(26) TF_ROUND(6)
    x0 += k2; x1 += k0 + 5u;
#undef TF_ROUND

    uint32_t bits = x0 ^ x1;
    return __uint_as_float((bits >> 9) | 0x3f800000u) - 1.0f;
}

// ---------------------------------------------------------------------------
// Row softmax (causal, scale 1/32) + JAX dropout, in place on g_s.
// ---------------------------------------------------------------------------
__global__ __launch_bounds__(256)
void softmax_dropout_kernel(float* __restrict__ S)
{
    const int i = blockIdx.x;
    const int t = threadIdx.x;
    const int len = i + 1;
    float* row = S + (size_t)i * NT;
    __shared__ float red[256];

    const float inv_scale = 0.03125f;  // 1/sqrt(1024)

    float lm = -INFINITY;
    for (int j = t; j < len; j += 256) lm = fmaxf(lm, row[j] * inv_scale);
    red[t] = lm; __syncthreads();
    for (int o = 128; o > 0; o >>= 1) {
        if (t < o) red[t] = fmaxf(red[t], red[t + o]);
        __syncthreads();
    }
    const float m = red[0];
    __syncthreads();

    float ls = 0.f;
    for (int j = t; j < len; j += 256) {
        float e = __expf(row[j] * inv_scale - m);
        row[j] = e;
        ls += e;
    }
    red[t] = ls; __syncthreads();
    for (int o = 128; o > 0; o >>= 1) {
        if (t < o) red[t] += red[t + o];
        __syncthreads();
    }
    const float inv_sum = 1.0f / red[0];
    const float keep_scale = inv_sum * (1.0f / 0.9f);

    const uint32_t base = (uint32_t)i * (uint32_t)NT;
    for (int j = t; j < NT; j += 256) {
        float w = 0.f;
        if (j < len) {
            float u = jax_uniform(base + (uint32_t)j);
            w = (u < 0.9f) ? row[j] * keep_scale : 0.f;
        }
        row[j] = w;
    }
}

// ---------------------------------------------------------------------------
extern "C" void kernel_launch(void* const* d_in, const int* in_sizes, int n_in,
                              void* d_out, int out_size)
{
    const float* x  = (const float*)d_in[0];
    const float* wq = (const float*)d_in[1];
    const float* wk = (const float*)d_in[2];
    const float* wv = (const float*)d_in[3];
    float* out = (float*)d_out;

    float *q, *k, *v, *s;
    cudaGetSymbolAddress((void**)&q, g_q);
    cudaGetSymbolAddress((void**)&k, g_k);
    cudaGetSymbolAddress((void**)&v, g_v);
    cudaGetSymbolAddress((void**)&s, g_s);

    // dynamic smem sizes (> 48KB needs opt-in; attribute set is idempotent)
    const int sh_nt = 2 * (128 * 36) * 2 * 4;               // 73728 B
    const int sh_nn = (2 * 128 * 36 + 2 * 32 * 136) * 4;    // 71680 B
    static bool attr_done = false;
    if (!attr_done) {
        cudaFuncSetAttribute(mma_nt_kernel<false>,
                             cudaFuncAttributeMaxDynamicSharedMemorySize, sh_nt);
        cudaFuncSetAttribute(mma_nt_kernel<true>,
                             cudaFuncAttributeMaxDynamicSharedMemorySize, sh_nt);
        cudaFuncSetAttribute(mma_nn_causal_kernel,
                             cudaFuncAttributeMaxDynamicSharedMemorySize, sh_nn);
        attr_done = true;
    }

    dim3 blk(256);

    dim3 grid_qkv(DM / 128, NT / 128);
    mma_nt_kernel<false><<<grid_qkv, blk, sh_nt>>>(x, wq, q, NT, DM, DM);
    mma_nt_kernel<false><<<grid_qkv, blk, sh_nt>>>(x, wk, k, NT, DM, DM);
    mma_nt_kernel<false><<<grid_qkv, blk, sh_nt>>>(x, wv, v, NT, DM, DM);

    dim3 grid_s(NT / 128, NT / 128);
    mma_nt_kernel<true><<<grid_s, blk, sh_nt>>>(q, k, s, NT, NT, DM);

    softmax_dropout_kernel<<<NT, blk>>>(s);

    dim3 grid_o(DM / 128, NT / 128);
    mma_nn_causal_kernel<<<grid_o, blk, sh_nn>>>(s, v, out, NT, DM, NT);
}

// round 6
// speedup vs baseline: 3.2380x; 1.1164x over previous
#include <cuda_runtime.h>
#include <cstdint>

#define NT 4096
#define DM 1024

// Scratch (static __device__ globals — allocation-free per harness rules)
__device__ float g_q[(size_t)NT * DM];
__device__ float g_k[(size_t)NT * DM];
__device__ float g_v[(size_t)NT * DM];
__device__ float g_s[(size_t)NT * NT];
__device__ float g_xr[(size_t)NT * DM];    // tf32-rounded x
__device__ float g_wqr[(size_t)DM * DM];   // tf32-rounded weights
__device__ float g_wkr[(size_t)DM * DM];
__device__ float g_wvr[(size_t)DM * DM];

__device__ __forceinline__ uint32_t f2tf32(float x)
{
    uint32_t y;
    asm("cvt.rna.tf32.f32 %0, %1;" : "=r"(y) : "f"(x));
    return y;
}
__device__ __forceinline__ float f2tf32f(float x)
{
    return __uint_as_float(f2tf32(x));
}

__device__ __forceinline__ void mma_tf32(float c[4], uint32_t a0, uint32_t a1,
                                         uint32_t a2, uint32_t a3,
                                         uint32_t b0, uint32_t b1)
{
    asm volatile(
        "mma.sync.aligned.m16n8k8.row.col.f32.tf32.tf32.f32 "
        "{%0,%1,%2,%3}, {%4,%5,%6,%7}, {%8,%9}, {%0,%1,%2,%3};"
        : "+f"(c[0]), "+f"(c[1]), "+f"(c[2]), "+f"(c[3])
        : "r"(a0), "r"(a1), "r"(a2), "r"(a3), "r"(b0), "r"(b1));
}

__device__ __forceinline__ void cp_async16(uint32_t dst_smem, const void* src)
{
    asm volatile("cp.async.cg.shared.global [%0], [%1], 16;\n"
                 :: "r"(dst_smem), "l"(src));
}
__device__ __forceinline__ void cp_commit()
{
    asm volatile("cp.async.commit_group;\n" ::: "memory");
}
__device__ __forceinline__ void cp_wait1()
{
    asm volatile("cp.async.wait_group 1;\n" ::: "memory");
}

// ---------------------------------------------------------------------------
// Elementwise tf32 pre-round (float4 vectorized)
// ---------------------------------------------------------------------------
__global__ __launch_bounds__(256)
void round_kernel(const float4* __restrict__ in, float4* __restrict__ out, int n4)
{
    int i = blockIdx.x * blockDim.x + threadIdx.x;
    if (i < n4) {
        float4 v = in[i];
        out[i] = make_float4(f2tf32f(v.x), f2tf32f(v.y), f2tf32f(v.z), f2tf32f(v.w));
    }
}

// ---------------------------------------------------------------------------
// tf32 MMA GEMM NT, 3-stage cp.async pipeline. Operands pre-rounded to tf32.
// C[M,N] = A[M,K] * B[N,K]^T. 128x128 tile, BK=32, 256 threads,
// 8 warps (2m x 4n of 64x32). Smem [row][k] stride 36 (conflict-free).
// CAUSAL skips blocks above diagonal; ROUND_OUT stores tf32-rounded output.
// ---------------------------------------------------------------------------
template<bool CAUSAL, bool ROUND_OUT>
__global__ __launch_bounds__(256, 2)
void mma_nt_kernel(const float* __restrict__ A, const float* __restrict__ B,
                   float* __restrict__ C, int M, int Ncols, int K)
{
    constexpr int BM = 128, BK = 32;
    constexpr int STR = BK + 4;                 // 36
    constexpr int TSZ = BM * STR;               // floats per operand per stage

    extern __shared__ float sm[];               // [3][2][128][36]

    const int bx = blockIdx.x, by = blockIdx.y;
    if (CAUSAL && bx > by) return;

    const int m0 = by * BM, n0 = bx * BM;
    const int t    = threadIdx.x;
    const int lane = t & 31, warp = t >> 5;
    const int wm = warp & 1, wn = warp >> 1;
    const int gID = lane >> 2, tig = lane & 3;

    const float* Ap = A + (size_t)m0 * K;
    const float* Bp = B + (size_t)n0 * K;
    const uint32_t sbase = (uint32_t)__cvta_generic_to_shared(sm);

    float c[4][4][4];
#pragma unroll
    for (int i = 0; i < 4; i++)
#pragma unroll
        for (int j = 0; j < 4; j++)
#pragma unroll
            for (int r = 0; r < 4; r++) c[i][j][r] = 0.f;

    auto issue = [&](int k0, int stg) {
        const uint32_t base = sbase + (uint32_t)(stg * 2 * TSZ) * 4u;
#pragma unroll
        for (int l = t; l < 1024; l += 256) {
            const int r  = l >> 3;
            const int cg = l & 7;
            cp_async16(base + (uint32_t)((r * STR + cg * 4) * 4),
                       Ap + (size_t)r * K + k0 + cg * 4);
            cp_async16(base + (uint32_t)((TSZ + r * STR + cg * 4) * 4),
                       Bp + (size_t)r * K + k0 + cg * 4);
        }
    };

    const int nk = K / BK;

    issue(0, 0);       cp_commit();
    issue(BK, 1);      cp_commit();

    for (int i = 0; i < nk; i++) {
        const int stg = i % 3;
        cp_wait1();
        __syncthreads();
        if (i + 2 < nk) {
            issue((i + 2) * BK, (i + 2) % 3);
            cp_commit();
        }

        const uint32_t* A0 = reinterpret_cast<const uint32_t*>(sm + stg * 2 * TSZ);
        const uint32_t* B0 = A0 + TSZ;
#pragma unroll
        for (int ks = 0; ks < 4; ks++) {
            const int kr = ks * 8;
            uint32_t a[4][4], b[4][2];
#pragma unroll
            for (int mt = 0; mt < 4; mt++) {
                const int r0 = wm * 64 + mt * 16 + gID;
                a[mt][0] = A0[r0 * STR + kr + tig];
                a[mt][1] = A0[(r0 + 8) * STR + kr + tig];
                a[mt][2] = A0[r0 * STR + kr + tig + 4];
                a[mt][3] = A0[(r0 + 8) * STR + kr + tig + 4];
            }
#pragma unroll
            for (int nt = 0; nt < 4; nt++) {
                const int c0 = wn * 32 + nt * 8 + gID;
                b[nt][0] = B0[c0 * STR + kr + tig];
                b[nt][1] = B0[c0 * STR + kr + tig + 4];
            }
#pragma unroll
            for (int mt = 0; mt < 4; mt++)
#pragma unroll
                for (int nt = 0; nt < 4; nt++)
                    mma_tf32(c[mt][nt], a[mt][0], a[mt][1], a[mt][2], a[mt][3],
                             b[nt][0], b[nt][1]);
        }
        __syncthreads();
    }

#pragma unroll
    for (int mt = 0; mt < 4; mt++) {
        const int row = m0 + wm * 64 + mt * 16 + gID;
#pragma unroll
        for (int nt = 0; nt < 4; nt++) {
            const int col = n0 + wn * 32 + nt * 8 + tig * 2;
            float o0 = ROUND_OUT ? f2tf32f(c[mt][nt][0]) : c[mt][nt][0];
            float o1 = ROUND_OUT ? f2tf32f(c[mt][nt][1]) : c[mt][nt][1];
            float o2 = ROUND_OUT ? f2tf32f(c[mt][nt][2]) : c[mt][nt][2];
            float o3 = ROUND_OUT ? f2tf32f(c[mt][nt][3]) : c[mt][nt][3];
            *reinterpret_cast<float2*>(C + (size_t)row * Ncols + col) = make_float2(o0, o1);
            *reinterpret_cast<float2*>(C + (size_t)(row + 8) * Ncols + col) = make_float2(o2, o3);
        }
    }
}

// ---------------------------------------------------------------------------
// tf32 MMA GEMM NN with causal k-limit, 3-stage cp.async pipeline.
// C[M,N] = A[M,K] * B[K,N], k < m0+BM. Operands pre-rounded.
// A smem [m][k] stride 36; B smem [k][n] stride 136.
// ---------------------------------------------------------------------------
__global__ __launch_bounds__(256, 2)
void mma_nn_causal_kernel(const float* __restrict__ A, const float* __restrict__ B,
                          float* __restrict__ C, int M, int Ncols, int K)
{
    constexpr int BM = 128, BN = 128, BK = 32;
    constexpr int STRA = BK + 4;                 // 36
    constexpr int STRB = BN + 8;                 // 136
    constexpr int TA = BM * STRA;                // 4608
    constexpr int TB = BK * STRB;                // 4352
    constexpr int TS = TA + TB;                  // floats per stage

    extern __shared__ float sm[];                // [3][TS]

    const int bx = blockIdx.x, by = blockIdx.y;
    const int m0 = by * BM, n0 = bx * BN;
    const int t    = threadIdx.x;
    const int lane = t & 31, warp = t >> 5;
    const int wm = warp & 1, wn = warp >> 1;
    const int gID = lane >> 2, tig = lane & 3;

    const float* Ap = A + (size_t)m0 * K;
    const uint32_t sbase = (uint32_t)__cvta_generic_to_shared(sm);

    float c[4][4][4];
#pragma unroll
    for (int i = 0; i < 4; i++)
#pragma unroll
        for (int j = 0; j < 4; j++)
#pragma unroll
            for (int r = 0; r < 4; r++) c[i][j][r] = 0.f;

    auto issue = [&](int k0, int stg) {
        const uint32_t base = sbase + (uint32_t)(stg * TS) * 4u;
#pragma unroll
        for (int l = t; l < 1024; l += 256) {
            {
                const int r  = l >> 3;
                const int cg = l & 7;
                cp_async16(base + (uint32_t)((r * STRA + cg * 4) * 4),
                           Ap + (size_t)r * K + k0 + cg * 4);
            }
            {
                const int kk = l >> 5;
                const int ng = l & 31;
                cp_async16(base + (uint32_t)((TA + kk * STRB + ng * 4) * 4),
                           B + (size_t)(k0 + kk) * Ncols + n0 + ng * 4);
            }
        }
    };

    const int kmax = min(K, m0 + BM);   // weights beyond row-tile are exact zeros
    const int nk = kmax / BK;           // >= 4 always

    issue(0, 0);   cp_commit();
    issue(BK, 1);  cp_commit();

    for (int i = 0; i < nk; i++) {
        const int stg = i % 3;
        cp_wait1();
        __syncthreads();
        if (i + 2 < nk) {
            issue((i + 2) * BK, (i + 2) % 3);
            cp_commit();
        }

        const uint32_t* A0 = reinterpret_cast<const uint32_t*>(sm + stg * TS);
        const uint32_t* B0 = A0 + TA;
#pragma unroll
        for (int ks = 0; ks < 4; ks++) {
            const int kr = ks * 8;
            uint32_t a[4][4], b[4][2];
#pragma unroll
            for (int mt = 0; mt < 4; mt++) {
                const int r0 = wm * 64 + mt * 16 + gID;
                a[mt][0] = A0[r0 * STRA + kr + tig];
                a[mt][1] = A0[(r0 + 8) * STRA + kr + tig];
                a[mt][2] = A0[r0 * STRA + kr + tig + 4];
                a[mt][3] = A0[(r0 + 8) * STRA + kr + tig + 4];
            }
#pragma unroll
            for (int nt = 0; nt < 4; nt++) {
                const int c0 = wn * 32 + nt * 8 + gID;
                b[nt][0] = B0[(kr + tig) * STRB + c0];
                b[nt][1] = B0[(kr + tig + 4) * STRB + c0];
            }
#pragma unroll
            for (int mt = 0; mt < 4; mt++)
#pragma unroll
                for (int nt = 0; nt < 4; nt++)
                    mma_tf32(c[mt][nt], a[mt][0], a[mt][1], a[mt][2], a[mt][3],
                             b[nt][0], b[nt][1]);
        }
        __syncthreads();
    }

#pragma unroll
    for (int mt = 0; mt < 4; mt++) {
        const int row = m0 + wm * 64 + mt * 16 + gID;
#pragma unroll
        for (int nt = 0; nt < 4; nt++) {
            const int col = n0 + wn * 32 + nt * 8 + tig * 2;
            *reinterpret_cast<float2*>(C + (size_t)row * Ncols + col) =
                make_float2(c[mt][nt][0], c[mt][nt][1]);
            *reinterpret_cast<float2*>(C + (size_t)(row + 8) * Ncols + col) =
                make_float2(c[mt][nt][2], c[mt][nt][3]);
        }
    }
}

// ---------------------------------------------------------------------------
// Exact JAX *partitionable* threefry2x32 uniform (key = (0, 42)).
// ---------------------------------------------------------------------------
__device__ __forceinline__ float jax_uniform(uint32_t idx)
{
    const uint32_t k0 = 0u, k1 = 42u;
    const uint32_t k2 = 0x1BD11BDAu ^ k0 ^ k1;

    uint32_t x0 = 0u  + k0;
    uint32_t x1 = idx + k1;

#define TF_ROUND(r) { x0 += x1; x1 = __funnelshift_l(x1, x1, (r)); x1 ^= x0; }
    TF_ROUND(13) TF_ROUND(15) TF_ROUND(26) TF_ROUND(6)
    x0 += k1; x1 += k2 + 1u;
    TF_ROUND(17) TF_ROUND(29) TF_ROUND(16) TF_ROUND(24)
    x0 += k2; x1 += k0 + 2u;
    TF_ROUND(13) TF_ROUND(15) TF_ROUND(26) TF_ROUND(6)
    x0 += k0; x1 += k1 + 3u;
    TF_ROUND(17) TF_ROUND(29) TF_ROUND(16) TF_ROUND(24)
    x0 += k1; x1 += k2 + 4u;
    TF_ROUND(13) TF_ROUND(15) TF_ROUND(26) TF_ROUND(6)
    x0 += k2; x1 += k0 + 5u;
#undef TF_ROUND

    uint32_t bits = x0 ^ x1;
    return __uint_as_float((bits >> 9) | 0x3f800000u) - 1.0f;
}

// ---------------------------------------------------------------------------
// Single-pass register-resident softmax (causal, /32) + JAX dropout.
// 256 threads per row, 16 values per thread. One gmem read, writes only
// j < round_up(len,128) (exactly the span the O-GEMM reads). Output weights
// are tf32-pre-rounded for the NN kernel.
// ---------------------------------------------------------------------------
__global__ __launch_bounds__(256)
void softmax_dropout_kernel(float* __restrict__ S)
{
    const int i = blockIdx.x;
    const int t = threadIdx.x;
    const int len = i + 1;
    const int wlimit = (len + 127) & ~127;
    float* row = S + (size_t)i * NT;

    const int warp = t >> 5, lane = t & 31;
    __shared__ float red_m[8], red_s[8];

    const float inv_scale = 0.03125f;  // 1/sqrt(1024)

    float vals[16];
    float lm = -INFINITY;
#pragma unroll
    for (int c = 0; c < 16; c++) {
        const int j = t + 256 * c;
        float x = (j < len) ? row[j] * inv_scale : -INFINITY;
        vals[c] = x;
        lm = fmaxf(lm, x);
    }
#pragma unroll
    for (int o = 16; o; o >>= 1) lm = fmaxf(lm, __shfl_xor_sync(~0u, lm, o));
    if (lane == 0) red_m[warp] = lm;
    __syncthreads();
    float m = red_m[0];
#pragma unroll
    for (int w = 1; w < 8; w++) m = fmaxf(m, red_m[w]);

    float ls = 0.f;
#pragma unroll
    for (int c = 0; c < 16; c++) {
        const int j = t + 256 * c;
        if (j < len) {
            float e = __expf(vals[c] - m);
            vals[c] = e;
            ls += e;
        }
    }
#pragma unroll
    for (int o = 16; o; o >>= 1) ls += __shfl_xor_sync(~0u, ls, o);
    if (lane == 0) red_s[warp] = ls;
    __syncthreads();
    float s = 0.f;
#pragma unroll
    for (int w = 0; w < 8; w++) s += red_s[w];

    const float keep_scale = (1.0f / 0.9f) / s;
    const uint32_t base = (uint32_t)i * (uint32_t)NT;
#pragma unroll
    for (int c = 0; c < 16; c++) {
        const int j = t + 256 * c;
        if (j < wlimit) {
            float w = 0.f;
            if (j < len) {
                float u = jax_uniform(base + (uint32_t)j);
                w = (u < 0.9f) ? f2tf32f(vals[c] * keep_scale) : 0.f;
            }
            row[j] = w;
        }
    }
}

// ---------------------------------------------------------------------------
extern "C" void kernel_launch(void* const* d_in, const int* in_sizes, int n_in,
                              void* d_out, int out_size)
{
    const float* x  = (const float*)d_in[0];
    const float* wq = (const float*)d_in[1];
    const float* wk = (const float*)d_in[2];
    const float* wv = (const float*)d_in[3];
    float* out = (float*)d_out;

    float *q, *k, *v, *s, *xr, *wqr, *wkr, *wvr;
    cudaGetSymbolAddress((void**)&q, g_q);
    cudaGetSymbolAddress((void**)&k, g_k);
    cudaGetSymbolAddress((void**)&v, g_v);
    cudaGetSymbolAddress((void**)&s, g_s);
    cudaGetSymbolAddress((void**)&xr, g_xr);
    cudaGetSymbolAddress((void**)&wqr, g_wqr);
    cudaGetSymbolAddress((void**)&wkr, g_wkr);
    cudaGetSymbolAddress((void**)&wvr, g_wvr);

    constexpr int sh_nt = 3 * 2 * (128 * 36) * 4;              // 110592 B
    constexpr int sh_nn = 3 * (128 * 36 + 32 * 136) * 4;       // 107520 B
    static bool attr_done = false;
    if (!attr_done) {
        cudaFuncSetAttribute(mma_nt_kernel<false, true>,
                             cudaFuncAttributeMaxDynamicSharedMemorySize, sh_nt);
        cudaFuncSetAttribute(mma_nt_kernel<true, false>,
                             cudaFuncAttributeMaxDynamicSharedMemorySize, sh_nt);
        cudaFuncSetAttribute(mma_nn_causal_kernel,
                             cudaFuncAttributeMaxDynamicSharedMemorySize, sh_nn);
        attr_done = true;
    }

    dim3 blk(256);

    // pre-round x and weights to tf32
    round_kernel<<<(NT * DM / 4 + 255) / 256, blk>>>((const float4*)x,  (float4*)xr,  NT * DM / 4);
    round_kernel<<<(DM * DM / 4 + 255) / 256, blk>>>((const float4*)wq, (float4*)wqr, DM * DM / 4);
    round_kernel<<<(DM * DM / 4 + 255) / 256, blk>>>((const float4*)wk, (float4*)wkr, DM * DM / 4);
    round_kernel<<<(DM * DM / 4 + 255) / 256, blk>>>((const float4*)wv, (float4*)wvr, DM * DM / 4);

    // QKV projections (outputs tf32-rounded)
    dim3 grid_qkv(DM / 128, NT / 128);
    mma_nt_kernel<false, true><<<grid_qkv, blk, sh_nt>>>(xr, wqr, q, NT, DM, DM);
    mma_nt_kernel<false, true><<<grid_qkv, blk, sh_nt>>>(xr, wkr, k, NT, DM, DM);
    mma_nt_kernel<false, true><<<grid_qkv, blk, sh_nt>>>(xr, wvr, v, NT, DM, DM);

    // scores = Q @ K^T (lower-triangular blocks; f32 output for softmax)
    dim3 grid_s(NT / 128, NT / 128);
    mma_nt_kernel<true, false><<<grid_s, blk, sh_nt>>>(q, k, s, NT, NT, DM);

    // softmax + dropout (writes tf32-rounded weights, zero-fills to tile edge)
    softmax_dropout_kernel<<<NT, blk>>>(s);

    // out = weights @ V (causal k-limit per row tile)
    dim3 grid_o(DM / 128, NT / 128);
    mma_nn_causal_kernel<<<grid_o, blk, sh_nn>>>(s, v, out, NT, DM, NT);
}

// round 8
// speedup vs baseline: 3.3168x; 1.0243x over previous
#include <cuda_runtime.h>
#include <cstdint>

#define NT 4096
#define DM 1024

// Scratch (static __device__ globals — allocation-free per harness rules)
__device__ float g_q[(size_t)NT * DM];
__device__ float g_k[(size_t)NT * DM];
__device__ float g_v[(size_t)NT * DM];
__device__ float g_s[(size_t)NT * NT];
__device__ float g_xr[(size_t)NT * DM];    // tf32-rounded x
__device__ float g_wqr[(size_t)DM * DM];   // tf32-rounded weights
__device__ float g_wkr[(size_t)DM * DM];
__device__ float g_wvr[(size_t)DM * DM];

__device__ __forceinline__ uint32_t f2tf32(float x)
{
    uint32_t y;
    asm("cvt.rna.tf32.f32 %0, %1;" : "=r"(y) : "f"(x));
    return y;
}
__device__ __forceinline__ float f2tf32f(float x)
{
    return __uint_as_float(f2tf32(x));
}

__device__ __forceinline__ void mma_tf32(float c[4], uint32_t a0, uint32_t a1,
                                         uint32_t a2, uint32_t a3,
                                         uint32_t b0, uint32_t b1)
{
    asm volatile(
        "mma.sync.aligned.m16n8k8.row.col.f32.tf32.tf32.f32 "
        "{%0,%1,%2,%3}, {%4,%5,%6,%7}, {%8,%9}, {%0,%1,%2,%3};"
        : "+f"(c[0]), "+f"(c[1]), "+f"(c[2]), "+f"(c[3])
        : "r"(a0), "r"(a1), "r"(a2), "r"(a3), "r"(b0), "r"(b1));
}

__device__ __forceinline__ void cp_async16(uint32_t dst_smem, const void* src)
{
    asm volatile("cp.async.cg.shared.global [%0], [%1], 16;\n"
                 :: "r"(dst_smem), "l"(src));
}
__device__ __forceinline__ void cp_commit()
{
    asm volatile("cp.async.commit_group;\n" ::: "memory");
}
__device__ __forceinline__ void cp_wait1()
{
    asm volatile("cp.async.wait_group 1;\n" ::: "memory");
}

// ---------------------------------------------------------------------------
// Elementwise tf32 pre-round (float4 vectorized)
// ---------------------------------------------------------------------------
__global__ __launch_bounds__(256)
void round_kernel(const float4* __restrict__ in, float4* __restrict__ out, int n4)
{
    int i = blockIdx.x * blockDim.x + threadIdx.x;
    if (i < n4) {
        float4 v = in[i];
        out[i] = make_float4(f2tf32f(v.x), f2tf32f(v.y), f2tf32f(v.z), f2tf32f(v.w));
    }
}

// ---------------------------------------------------------------------------
// tf32 MMA GEMM NT, 3-stage cp.async pipeline, ONE barrier per k-chunk.
// C[M,N] = A[M,K] * B[N,K]^T. 128x128 tile, BK=32, 256 threads,
// 8 warps (2m x 4n of 64x32). Operands pre-rounded to tf32.
// blockIdx.z selects (B, C) pair — QKV projections fuse into one launch.
// CAUSAL skips blocks above diagonal; ROUND_OUT stores tf32-rounded output.
// ---------------------------------------------------------------------------
template<bool CAUSAL, bool ROUND_OUT>
__global__ __launch_bounds__(256, 2)
void mma_nt_kernel(const float* __restrict__ A,
                   const float* __restrict__ B0, const float* __restrict__ B1,
                   const float* __restrict__ B2,
                   float* __restrict__ C0, float* __restrict__ C1,
                   float* __restrict__ C2,
                   int M, int Ncols, int K)
{
    constexpr int BM = 128, BK = 32;
    constexpr int STR = BK + 4;                 // 36
    constexpr int TSZ = BM * STR;               // floats per operand per stage

    extern __shared__ float sm[];               // [3][2][128][36]

    const int bx = blockIdx.x, by = blockIdx.y, bz = blockIdx.z;
    if (CAUSAL && bx > by) return;

    const float* __restrict__ B = (bz == 0) ? B0 : (bz == 1) ? B1 : B2;
    float* __restrict__ C       = (bz == 0) ? C0 : (bz == 1) ? C1 : C2;

    const int m0 = by * BM, n0 = bx * BM;
    const int t    = threadIdx.x;
    const int lane = t & 31, warp = t >> 5;
    const int wm = warp & 1, wn = warp >> 1;
    const int gID = lane >> 2, tig = lane & 3;

    const float* Ap = A + (size_t)m0 * K;
    const float* Bp = B + (size_t)n0 * K;
    const uint32_t sbase = (uint32_t)__cvta_generic_to_shared(sm);

    float c[4][4][4];
#pragma unroll
    for (int i = 0; i < 4; i++)
#pragma unroll
        for (int j = 0; j < 4; j++)
#pragma unroll
            for (int r = 0; r < 4; r++) c[i][j][r] = 0.f;

    auto issue = [&](int k0, int stg) {
        const uint32_t base = sbase + (uint32_t)(stg * 2 * TSZ) * 4u;
#pragma unroll
        for (int l = t; l < 1024; l += 256) {
            const int r  = l >> 3;
            const int cg = l & 7;
            cp_async16(base + (uint32_t)((r * STR + cg * 4) * 4),
                       Ap + (size_t)r * K + k0 + cg * 4);
            cp_async16(base + (uint32_t)((TSZ + r * STR + cg * 4) * 4),
                       Bp + (size_t)r * K + k0 + cg * 4);
        }
    };

    const int nk = K / BK;

    issue(0, 0);       cp_commit();
    issue(BK, 1);      cp_commit();

    for (int i = 0; i < nk; i++) {
        const int stg = i % 3;
        cp_wait1();
        __syncthreads();                 // sole barrier: readers of slot (i-1)%3 done
        if (i + 2 < nk)
            issue((i + 2) * BK, (i + 2) % 3);   // writes slot (i+2)%3 == (i-1)%3
        cp_commit();                     // uniform group numbering (may be empty)

        const uint32_t* A0 = reinterpret_cast<const uint32_t*>(sm + stg * 2 * TSZ);
        const uint32_t* B0s = A0 + TSZ;
#pragma unroll
        for (int ks = 0; ks < 4; ks++) {
            const int kr = ks * 8;
            uint32_t a[4][4], b[4][2];
#pragma unroll
            for (int mt = 0; mt < 4; mt++) {
                const int r0 = wm * 64 + mt * 16 + gID;
                a[mt][0] = A0[r0 * STR + kr + tig];
                a[mt][1] = A0[(r0 + 8) * STR + kr + tig];
                a[mt][2] = A0[r0 * STR + kr + tig + 4];
                a[mt][3] = A0[(r0 + 8) * STR + kr + tig + 4];
            }
#pragma unroll
            for (int nt = 0; nt < 4; nt++) {
                const int c0 = wn * 32 + nt * 8 + gID;
                b[nt][0] = B0s[c0 * STR + kr + tig];
                b[nt][1] = B0s[c0 * STR + kr + tig + 4];
            }
#pragma unroll
            for (int mt = 0; mt < 4; mt++)
#pragma unroll
                for (int nt = 0; nt < 4; nt++)
                    mma_tf32(c[mt][nt], a[mt][0], a[mt][1], a[mt][2], a[mt][3],
                             b[nt][0], b[nt][1]);
        }
        // no trailing barrier — top-of-loop barrier covers the slot-reuse hazard
    }

#pragma unroll
    for (int mt = 0; mt < 4; mt++) {
        const int row = m0 + wm * 64 + mt * 16 + gID;
#pragma unroll
        for (int nt = 0; nt < 4; nt++) {
            const int col = n0 + wn * 32 + nt * 8 + tig * 2;
            float o0 = ROUND_OUT ? f2tf32f(c[mt][nt][0]) : c[mt][nt][0];
            float o1 = ROUND_OUT ? f2tf32f(c[mt][nt][1]) : c[mt][nt][1];
            float o2 = ROUND_OUT ? f2tf32f(c[mt][nt][2]) : c[mt][nt][2];
            float o3 = ROUND_OUT ? f2tf32f(c[mt][nt][3]) : c[mt][nt][3];
            *reinterpret_cast<float2*>(C + (size_t)row * Ncols + col) = make_float2(o0, o1);
            *reinterpret_cast<float2*>(C + (size_t)(row + 8) * Ncols + col) = make_float2(o2, o3);
        }
    }
}

// ---------------------------------------------------------------------------
// tf32 MMA GEMM NN with causal k-limit, 3-stage cp.async pipeline, one barrier.
// C[M,N] = A[M,K] * B[K,N], k < m0+BM. Operands pre-rounded.
// A smem [m][k] stride 36; B smem [k][n] stride 136.
// ---------------------------------------------------------------------------
__global__ __launch_bounds__(256, 2)
void mma_nn_causal_kernel(const float* __restrict__ A, const float* __restrict__ B,
                          float* __restrict__ C, int M, int Ncols, int K)
{
    constexpr int BM = 128, BN = 128, BK = 32;
    constexpr int STRA = BK + 4;                 // 36
    constexpr int STRB = BN + 8;                 // 136
    constexpr int TA = BM * STRA;                // 4608
    constexpr int TB = BK * STRB;                // 4352
    constexpr int TS = TA + TB;                  // floats per stage

    extern __shared__ float sm[];                // [3][TS]

    const int bx = blockIdx.x, by = blockIdx.y;
    const int m0 = by * BM, n0 = bx * BN;
    const int t    = threadIdx.x;
    const int lane = t & 31, warp = t >> 5;
    const int wm = warp & 1, wn = warp >> 1;
    const int gID = lane >> 2, tig = lane & 3;

    const float* Ap = A + (size_t)m0 * K;
    const uint32_t sbase = (uint32_t)__cvta_generic_to_shared(sm);

    float c[4][4][4];
#pragma unroll
    for (int i = 0; i < 4; i++)
#pragma unroll
        for (int j = 0; j < 4; j++)
#pragma unroll
            for (int r = 0; r < 4; r++) c[i][j][r] = 0.f;

    auto issue = [&](int k0, int stg) {
        const uint32_t base = sbase + (uint32_t)(stg * TS) * 4u;
#pragma unroll
        for (int l = t; l < 1024; l += 256) {
            {
                const int r  = l >> 3;
                const int cg = l & 7;
                cp_async16(base + (uint32_t)((r * STRA + cg * 4) * 4),
                           Ap + (size_t)r * K + k0 + cg * 4);
            }
            {
                const int kk = l >> 5;
                const int ng = l & 31;
                cp_async16(base + (uint32_t)((TA + kk * STRB + ng * 4) * 4),
                           B + (size_t)(k0 + kk) * Ncols + n0 + ng * 4);
            }
        }
    };

    const int kmax = min(K, m0 + BM);   // weights beyond row-tile are exact zeros
    const int nk = kmax / BK;           // >= 4 always

    issue(0, 0);   cp_commit();
    issue(BK, 1);  cp_commit();

    for (int i = 0; i < nk; i++) {
        const int stg = i % 3;
        cp_wait1();
        __syncthreads();
        if (i + 2 < nk)
            issue((i + 2) * BK, (i + 2) % 3);
        cp_commit();

        const uint32_t* A0 = reinterpret_cast<const uint32_t*>(sm + stg * TS);
        const uint32_t* B0 = A0 + TA;
#pragma unroll
        for (int ks = 0; ks < 4; ks++) {
            const int kr = ks * 8;
            uint32_t a[4][4], b[4][2];
#pragma unroll
            for (int mt = 0; mt < 4; mt++) {
                const int r0 = wm * 64 + mt * 16 + gID;
                a[mt][0] = A0[r0 * STRA + kr + tig];
                a[mt][1] = A0[(r0 + 8) * STRA + kr + tig];
                a[mt][2] = A0[r0 * STRA + kr + tig + 4];
                a[mt][3] = A0[(r0 + 8) * STRA + kr + tig + 4];
            }
#pragma unroll
            for (int nt = 0; nt < 4; nt++) {
                const int c0 = wn * 32 + nt * 8 + gID;
                b[nt][0] = B0[(kr + tig) * STRB + c0];
                b[nt][1] = B0[(kr + tig + 4) * STRB + c0];
            }
#pragma unroll
            for (int mt = 0; mt < 4; mt++)
#pragma unroll
                for (int nt = 0; nt < 4; nt++)
                    mma_tf32(c[mt][nt], a[mt][0], a[mt][1], a[mt][2], a[mt][3],
                             b[nt][0], b[nt][1]);
        }
    }

#pragma unroll
    for (int mt = 0; mt < 4; mt++) {
        const int row = m0 + wm * 64 + mt * 16 + gID;
#pragma unroll
        for (int nt = 0; nt < 4; nt++) {
            const int col = n0 + wn * 32 + nt * 8 + tig * 2;
            *reinterpret_cast<float2*>(C + (size_t)row * Ncols + col) =
                make_float2(c[mt][nt][0], c[mt][nt][1]);
            *reinterpret_cast<float2*>(C + (size_t)(row + 8) * Ncols + col) =
                make_float2(c[mt][nt][2], c[mt][nt][3]);
        }
    }
}

// ---------------------------------------------------------------------------
// Exact JAX *partitionable* threefry2x32 uniform (key = (0, 42)).
// ---------------------------------------------------------------------------
__device__ __forceinline__ float jax_uniform(uint32_t idx)
{
    const uint32_t k0 = 0u, k1 = 42u;
    const uint32_t k2 = 0x1BD11BDAu ^ k0 ^ k1;

    uint32_t x0 = 0u  + k0;
    uint32_t x1 = idx + k1;

#define TF_ROUND(r) { x0 += x1; x1 = __funnelshift_l(x1, x1, (r)); x1 ^= x0; }
    TF_ROUND(13) TF_ROUND(15) TF_ROUND(26) TF_ROUND(6)
    x0 += k1; x1 += k2 + 1u;
    TF_ROUND(17) TF_ROUND(29) TF_ROUND(16) TF_ROUND(24)
    x0 += k2; x1 += k0 + 2u;
    TF_ROUND(13) TF_ROUND(15) TF_ROUND(26) TF_ROUND(6)
    x0 += k0; x1 += k1 + 3u;
    TF_ROUND(17) TF_ROUND(29) TF_ROUND(16) TF_ROUND(24)
    x0 += k1; x1 += k2 + 4u;
    TF_ROUND(13) TF_ROUND(15) TF_ROUND(26) TF_ROUND(6)
    x0 += k2; x1 += k0 + 5u;
#undef TF_ROUND

    uint32_t bits = x0 ^ x1;
    return __uint_as_float((bits >> 9) | 0x3f800000u) - 1.0f;
}

// ---------------------------------------------------------------------------
// Single-pass register-resident softmax (causal, /32) + JAX dropout.
// Writes tf32-rounded weights; zero-fills to round_up(len,128) — exactly
// the span the O-GEMM's causal k-limit reads.
// ---------------------------------------------------------------------------
__global__ __launch_bounds__(256)
void softmax_dropout_kernel(float* __restrict__ S)
{
    const int i = blockIdx.x;
    const int t = threadIdx.x;
    const int len = i + 1;
    const int wlimit = (len + 127) & ~127;
    float* row = S + (size_t)i * NT;

    const int warp = t >> 5, lane = t & 31;
    __shared__ float red_m[8], red_s[8];

    const float inv_scale = 0.03125f;  // 1/sqrt(1024)

    float vals[16];
    float lm = -INFINITY;
#pragma unroll
    for (int c = 0; c < 16; c++) {
        const int j = t + 256 * c;
        float x = (j < len) ? row[j] * inv_scale : -INFINITY;
        vals[c] = x;
        lm = fmaxf(lm, x);
    }
#pragma unroll
    for (int o = 16; o; o >>= 1) lm = fmaxf(lm, __shfl_xor_sync(~0u, lm, o));
    if (lane == 0) red_m[warp] = lm;
    __syncthreads();
    float m = red_m[0];
#pragma unroll
    for (int w = 1; w < 8; w++) m = fmaxf(m, red_m[w]);

    float ls = 0.f;
#pragma unroll
    for (int c = 0; c < 16; c++) {
        const int j = t + 256 * c;
        if (j < len) {
            float e = __expf(vals[c] - m);
            vals[c] = e;
            ls += e;
        }
    }
#pragma unroll
    for (int o = 16; o; o >>= 1) ls += __shfl_xor_sync(~0u, ls, o);
    if (lane == 0) red_s[warp] = ls;
    __syncthreads();
    float s = 0.f;
#pragma unroll
    for (int w = 0; w < 8; w++) s += red_s[w];

    const float keep_scale = (1.0f / 0.9f) / s;
    const uint32_t base = (uint32_t)i * (uint32_t)NT;
#pragma unroll
    for (int c = 0; c < 16; c++) {
        const int j = t + 256 * c;
        if (j < wlimit) {
            float w = 0.f;
            if (j < len) {
                float u = jax_uniform(base + (uint32_t)j);
                w = (u < 0.9f) ? f2tf32f(vals[c] * keep_scale) : 0.f;
            }
            row[j] = w;
        }
    }
}

// ---------------------------------------------------------------------------
extern "C" void kernel_launch(void* const* d_in, const int* in_sizes, int n_in,
                              void* d_out, int out_size)
{
    const float* x  = (const float*)d_in[0];
    const float* wq = (const float*)d_in[1];
    const float* wk = (const float*)d_in[2];
    const float* wv = (const float*)d_in[3];
    float* out = (float*)d_out;

    float *q, *k, *v, *s, *xr, *wqr, *wkr, *wvr;
    cudaGetSymbolAddress((void**)&q, g_q);
    cudaGetSymbolAddress((void**)&k, g_k);
    cudaGetSymbolAddress((void**)&v, g_v);
    cudaGetSymbolAddress((void**)&s, g_s);
    cudaGetSymbolAddress((void**)&xr, g_xr);
    cudaGetSymbolAddress((void**)&wqr, g_wqr);
    cudaGetSymbolAddress((void**)&wkr, g_wkr);
    cudaGetSymbolAddress((void**)&wvr, g_wvr);

    constexpr int sh_nt = 3 * 2 * (128 * 36) * 4;              // 110592 B
    constexpr int sh_nn = 3 * (128 * 36 + 32 * 136) * 4;       // 107520 B
    static bool attr_done = false;
    if (!attr_done) {
        cudaFuncSetAttribute(mma_nt_kernel<false, true>,
                             cudaFuncAttributeMaxDynamicSharedMemorySize, sh_nt);
        cudaFuncSetAttribute(mma_nt_kernel<true, false>,
                             cudaFuncAttributeMaxDynamicSharedMemorySize, sh_nt);
        cudaFuncSetAttribute(mma_nn_causal_kernel,
                             cudaFuncAttributeMaxDynamicSharedMemorySize, sh_nn);
        attr_done = true;
    }

    dim3 blk(256);

    // pre-round x and weights to tf32
    round_kernel<<<(NT * DM / 4 + 255) / 256, blk>>>((const float4*)x,  (float4*)xr,  NT * DM / 4);
    round_kernel<<<(DM * DM / 4 + 255) / 256, blk>>>((const float4*)wq, (float4*)wqr, DM * DM / 4);
    round_kernel<<<(DM * DM / 4 + 255) / 256, blk>>>((const float4*)wk, (float4*)wkr, DM * DM / 4);
    round_kernel<<<(DM * DM / 4 + 255) / 256, blk>>>((const float4*)wv, (float4*)wvr, DM * DM / 4);

    // QKV projections fused into one launch via grid.z (outputs tf32-rounded)
    dim3 grid_qkv(DM / 128, NT / 128, 3);
    mma_nt_kernel<false, true><<<grid_qkv, blk, sh_nt>>>(
        xr, wqr, wkr, wvr, q, k, v, NT, DM, DM);

    // scores = Q @ K^T (lower-triangular blocks; f32 output for softmax)
    dim3 grid_s(NT / 128, NT / 128, 1);
    mma_nt_kernel<true, false><<<grid_s, blk, sh_nt>>>(
        q, k, k, k, s, s, s, NT, NT, DM);

    // softmax + dropout (writes tf32-rounded weights, zero-fills to tile edge)
    softmax_dropout_kernel<<<NT, blk>>>(s);

    // out = weights @ V (causal k-limit per row tile)
    dim3 grid_o(DM / 128, NT / 128);
    mma_nn_causal_kernel<<<grid_o, blk, sh_nn>>>(s, v, out, NT, DM, NT);
}

// round 9
// speedup vs baseline: 3.4095x; 1.0280x over previous
#include <cuda_runtime.h>
#include <cstdint>

#define NT 4096
#define DM 1024

// Scratch (static __device__ globals — allocation-free per harness rules)
__device__ float g_q[(size_t)NT * DM];
__device__ float g_k[(size_t)NT * DM];
__device__ float g_v[(size_t)NT * DM];
__device__ float g_s[(size_t)NT * NT];
__device__ float g_xr[(size_t)NT * DM];    // tf32-rounded x
__device__ float g_wqr[(size_t)DM * DM];   // tf32-rounded weights
__device__ float g_wkr[(size_t)DM * DM];
__device__ float g_wvr[(size_t)DM * DM];

__device__ __forceinline__ uint32_t f2tf32(float x)
{
    uint32_t y;
    asm("cvt.rna.tf32.f32 %0, %1;" : "=r"(y) : "f"(x));
    return y;
}
__device__ __forceinline__ float f2tf32f(float x)
{
    return __uint_as_float(f2tf32(x));
}

__device__ __forceinline__ void mma_tf32(float c[4], uint32_t a0, uint32_t a1,
                                         uint32_t a2, uint32_t a3,
                                         uint32_t b0, uint32_t b1)
{
    asm volatile(
        "mma.sync.aligned.m16n8k8.row.col.f32.tf32.tf32.f32 "
        "{%0,%1,%2,%3}, {%4,%5,%6,%7}, {%8,%9}, {%0,%1,%2,%3};"
        : "+f"(c[0]), "+f"(c[1]), "+f"(c[2]), "+f"(c[3])
        : "r"(a0), "r"(a1), "r"(a2), "r"(a3), "r"(b0), "r"(b1));
}

__device__ __forceinline__ void cp_async16(uint32_t dst_smem, const void* src)
{
    asm volatile("cp.async.cg.shared.global [%0], [%1], 16;\n"
                 :: "r"(dst_smem), "l"(src));
}
__device__ __forceinline__ void cp_commit()
{
    asm volatile("cp.async.commit_group;\n" ::: "memory");
}
__device__ __forceinline__ void cp_wait1()
{
    asm volatile("cp.async.wait_group 1;\n" ::: "memory");
}
__device__ __forceinline__ void cp_wait2()
{
    asm volatile("cp.async.wait_group 2;\n" ::: "memory");
}

// ---------------------------------------------------------------------------
// Elementwise tf32 pre-round (float4 vectorized)
// ---------------------------------------------------------------------------
__global__ __launch_bounds__(256)
void round_kernel(const float4* __restrict__ in, float4* __restrict__ out, int n4)
{
    int i = blockIdx.x * blockDim.x + threadIdx.x;
    if (i < n4) {
        float4 v = in[i];
        out[i] = make_float4(f2tf32f(v.x), f2tf32f(v.y), f2tf32f(v.z), f2tf32f(v.w));
    }
}

// ---------------------------------------------------------------------------
// tf32 MMA GEMM NT. CTA tile 128x256, 8 warps of 64x64 (2m x 4n), BK=32,
// 4-stage cp.async pipeline (preload 3, wait_group 2), one barrier/iter.
// C[M,N] = A[M,K] * B[N,K]^T, operands pre-rounded to tf32.
// blockIdx.z selects (B, C) pair — QKV projections fuse into one launch.
// CAUSAL: keep block iff 2*bx <= by (256-wide cols vs 128-tall rows).
// ROUND_OUT stores tf32-rounded output.
// ---------------------------------------------------------------------------
template<bool CAUSAL, bool ROUND_OUT>
__global__ __launch_bounds__(256)
void mma_nt_kernel(const float* __restrict__ A,
                   const float* __restrict__ B0, const float* __restrict__ B1,
                   const float* __restrict__ B2,
                   float* __restrict__ C0, float* __restrict__ C1,
                   float* __restrict__ C2,
                   int M, int Ncols, int K)
{
    constexpr int BM = 128, BN = 256, BK = 32;
    constexpr int STR = BK + 4;                 // 36: conflict-free for frag loads
    constexpr int TA = BM * STR;                // 4608 floats
    constexpr int TB = BN * STR;                // 9216 floats
    constexpr int TS = TA + TB;                 // 13824 floats = 55296 B / stage
    constexpr int NS = 4, PRE = 3;

    extern __shared__ float sm[];               // [4][TS]

    const int bx = blockIdx.x, by = blockIdx.y, bz = blockIdx.z;
    if (CAUSAL && 2 * bx > by) return;

    const float* __restrict__ B = (bz == 0) ? B0 : (bz == 1) ? B1 : B2;
    float* __restrict__ C       = (bz == 0) ? C0 : (bz == 1) ? C1 : C2;

    const int m0 = by * BM, n0 = bx * BN;
    const int t    = threadIdx.x;
    const int lane = t & 31, warp = t >> 5;
    const int wm = warp & 1, wn = warp >> 1;    // 2m x 4n, 64x64 each
    const int gID = lane >> 2, tig = lane & 3;

    const float* Ap = A + (size_t)m0 * K;
    const float* Bp = B + (size_t)n0 * K;
    const uint32_t sbase = (uint32_t)__cvta_generic_to_shared(sm);

    float c[4][8][4];
#pragma unroll
    for (int i = 0; i < 4; i++)
#pragma unroll
        for (int j = 0; j < 8; j++)
#pragma unroll
            for (int r = 0; r < 4; r++) c[i][j][r] = 0.f;

    auto issue = [&](int k0, int stg) {
        const uint32_t base = sbase + (uint32_t)(stg * TS) * 4u;
#pragma unroll
        for (int l = t; l < 1024; l += 256) {       // A: 128 rows x 8 chunks
            const int r  = l >> 3;
            const int cg = l & 7;
            cp_async16(base + (uint32_t)((r * STR + cg * 4) * 4),
                       Ap + (size_t)r * K + k0 + cg * 4);
        }
#pragma unroll
        for (int l = t; l < 2048; l += 256) {       // B: 256 rows x 8 chunks
            const int r  = l >> 3;
            const int cg = l & 7;
            cp_async16(base + (uint32_t)((TA + r * STR + cg * 4) * 4),
                       Bp + (size_t)r * K + k0 + cg * 4);
        }
    };

    const int nk = K / BK;                      // 32 for K=1024

    issue(0, 0);       cp_commit();
    issue(BK, 1);      cp_commit();
    issue(2 * BK, 2);  cp_commit();

    for (int i = 0; i < nk; i++) {
        const int stg = i & 3;
        cp_wait2();                              // stage i resident
        __syncthreads();                         // readers of slot (i-1)&3 retired
        if (i + PRE < nk)
            issue((i + PRE) * BK, (i + PRE) & 3);  // writes slot (i-1)&3
        cp_commit();                             // uniform group numbering

        const uint32_t* A0 = reinterpret_cast<const uint32_t*>(sm + stg * TS);
        const uint32_t* B0s = A0 + TA;
#pragma unroll
        for (int ks = 0; ks < 4; ks++) {
            const int kr = ks * 8;
            uint32_t a[4][4], b[8][2];
#pragma unroll
            for (int mt = 0; mt < 4; mt++) {
                const int r0 = wm * 64 + mt * 16 + gID;
                a[mt][0] = A0[r0 * STR + kr + tig];
                a[mt][1] = A0[(r0 + 8) * STR + kr + tig];
                a[mt][2] = A0[r0 * STR + kr + tig + 4];
                a[mt][3] = A0[(r0 + 8) * STR + kr + tig + 4];
            }
#pragma unroll
            for (int nt = 0; nt < 8; nt++) {
                const int c0 = wn * 64 + nt * 8 + gID;
                b[nt][0] = B0s[c0 * STR + kr + tig];
                b[nt][1] = B0s[c0 * STR + kr + tig + 4];
            }
#pragma unroll
            for (int mt = 0; mt < 4; mt++)
#pragma unroll
                for (int nt = 0; nt < 8; nt++)
                    mma_tf32(c[mt][nt], a[mt][0], a[mt][1], a[mt][2], a[mt][3],
                             b[nt][0], b[nt][1]);
        }
    }

#pragma unroll
    for (int mt = 0; mt < 4; mt++) {
        const int row = m0 + wm * 64 + mt * 16 + gID;
#pragma unroll
        for (int nt = 0; nt < 8; nt++) {
            const int col = n0 + wn * 64 + nt * 8 + tig * 2;
            float o0 = ROUND_OUT ? f2tf32f(c[mt][nt][0]) : c[mt][nt][0];
            float o1 = ROUND_OUT ? f2tf32f(c[mt][nt][1]) : c[mt][nt][1];
            float o2 = ROUND_OUT ? f2tf32f(c[mt][nt][2]) : c[mt][nt][2];
            float o3 = ROUND_OUT ? f2tf32f(c[mt][nt][3]) : c[mt][nt][3];
            *reinterpret_cast<float2*>(C + (size_t)row * Ncols + col) = make_float2(o0, o1);
            *reinterpret_cast<float2*>(C + (size_t)(row + 8) * Ncols + col) = make_float2(o2, o3);
        }
    }
}

// ---------------------------------------------------------------------------
// tf32 MMA GEMM NN with causal k-limit, 3-stage cp.async pipeline, one barrier.
// C[M,N] = A[M,K] * B[K,N], k < m0+BM. Operands pre-rounded.
// A smem [m][k] stride 36; B smem [k][n] stride 136. (proven R6/R8 kernel)
// ---------------------------------------------------------------------------
__global__ __launch_bounds__(256, 2)
void mma_nn_causal_kernel(const float* __restrict__ A, const float* __restrict__ B,
                          float* __restrict__ C, int M, int Ncols, int K)
{
    constexpr int BM = 128, BN = 128, BK = 32;
    constexpr int STRA = BK + 4;                 // 36
    constexpr int STRB = BN + 8;                 // 136
    constexpr int TA = BM * STRA;                // 4608
    constexpr int TB = BK * STRB;                // 4352
    constexpr int TS = TA + TB;

    extern __shared__ float sm[];                // [3][TS]

    const int bx = blockIdx.x, by = blockIdx.y;
    const int m0 = by * BM, n0 = bx * BN;
    const int t    = threadIdx.x;
    const int lane = t & 31, warp = t >> 5;
    const int wm = warp & 1, wn = warp >> 1;
    const int gID = lane >> 2, tig = lane & 3;

    const float* Ap = A + (size_t)m0 * K;
    const uint32_t sbase = (uint32_t)__cvta_generic_to_shared(sm);

    float c[4][4][4];
#pragma unroll
    for (int i = 0; i < 4; i++)
#pragma unroll
        for (int j = 0; j < 4; j++)
#pragma unroll
            for (int r = 0; r < 4; r++) c[i][j][r] = 0.f;

    auto issue = [&](int k0, int stg) {
        const uint32_t base = sbase + (uint32_t)(stg * TS) * 4u;
#pragma unroll
        for (int l = t; l < 1024; l += 256) {
            {
                const int r  = l >> 3;
                const int cg = l & 7;
                cp_async16(base + (uint32_t)((r * STRA + cg * 4) * 4),
                           Ap + (size_t)r * K + k0 + cg * 4);
            }
            {
                const int kk = l >> 5;
                const int ng = l & 31;
                cp_async16(base + (uint32_t)((TA + kk * STRB + ng * 4) * 4),
                           B + (size_t)(k0 + kk) * Ncols + n0 + ng * 4);
            }
        }
    };

    const int kmax = min(K, m0 + BM);
    const int nk = kmax / BK;                    // >= 4 always

    issue(0, 0);   cp_commit();
    issue(BK, 1);  cp_commit();

    for (int i = 0; i < nk; i++) {
        const int stg = i % 3;
        cp_wait1();
        __syncthreads();
        if (i + 2 < nk)
            issue((i + 2) * BK, (i + 2) % 3);
        cp_commit();

        const uint32_t* A0 = reinterpret_cast<const uint32_t*>(sm + stg * TS);
        const uint32_t* B0 = A0 + TA;
#pragma unroll
        for (int ks = 0; ks < 4; ks++) {
            const int kr = ks * 8;
            uint32_t a[4][4], b[4][2];
#pragma unroll
            for (int mt = 0; mt < 4; mt++) {
                const int r0 = wm * 64 + mt * 16 + gID;
                a[mt][0] = A0[r0 * STRA + kr + tig];
                a[mt][1] = A0[(r0 + 8) * STRA + kr + tig];
                a[mt][2] = A0[r0 * STRA + kr + tig + 4];
                a[mt][3] = A0[(r0 + 8) * STRA + kr + tig + 4];
            }
#pragma unroll
            for (int nt = 0; nt < 4; nt++) {
                const int c0 = wn * 32 + nt * 8 + gID;
                b[nt][0] = B0[(kr + tig) * STRB + c0];
                b[nt][1] = B0[(kr + tig + 4) * STRB + c0];
            }
#pragma unroll
            for (int mt = 0; mt < 4; mt++)
#pragma unroll
                for (int nt = 0; nt < 4; nt++)
                    mma_tf32(c[mt][nt], a[mt][0], a[mt][1], a[mt][2], a[mt][3],
                             b[nt][0], b[nt][1]);
        }
    }

#pragma unroll
    for (int mt = 0; mt < 4; mt++) {
        const int row = m0 + wm * 64 + mt * 16 + gID;
#pragma unroll
        for (int nt = 0; nt < 4; nt++) {
            const int col = n0 + wn * 32 + nt * 8 + tig * 2;
            *reinterpret_cast<float2*>(C + (size_t)row * Ncols + col) =
                make_float2(c[mt][nt][0], c[mt][nt][1]);
            *reinterpret_cast<float2*>(C + (size_t)(row + 8) * Ncols + col) =
                make_float2(c[mt][nt][2], c[mt][nt][3]);
        }
    }
}

// ---------------------------------------------------------------------------
// Exact JAX *partitionable* threefry2x32 uniform (key = (0, 42)).
// ---------------------------------------------------------------------------
__device__ __forceinline__ float jax_uniform(uint32_t idx)
{
    const uint32_t k0 = 0u, k1 = 42u;
    const uint32_t k2 = 0x1BD11BDAu ^ k0 ^ k1;

    uint32_t x0 = 0u  + k0;
    uint32_t x1 = idx + k1;

#define TF_ROUND(r) { x0 += x1; x1 = __funnelshift_l(x1, x1, (r)); x1 ^= x0; }
    TF_ROUND(13) TF_ROUND(15) TF_ROUND(26) TF_ROUND(6)
    x0 += k1; x1 += k2 + 1u;
    TF_ROUND(17) TF_ROUND(29) TF_ROUND(16) TF_ROUND(24)
    x0 += k2; x1 += k0 + 2u;
    TF_ROUND(13) TF_ROUND(15) TF_ROUND(26) TF_ROUND(6)
    x0 += k0; x1 += k1 + 3u;
    TF_ROUND(17) TF_ROUND(29) TF_ROUND(16) TF_ROUND(24)
    x0 += k1; x1 += k2 + 4u;
    TF_ROUND(13) TF_ROUND(15) TF_ROUND(26) TF_ROUND(6)
    x0 += k2; x1 += k0 + 5u;
#undef TF_ROUND

    uint32_t bits = x0 ^ x1;
    return __uint_as_float((bits >> 9) | 0x3f800000u) - 1.0f;
}

// ---------------------------------------------------------------------------
// Single-pass register-resident softmax (causal, /32) + JAX dropout.
// Writes tf32-rounded weights; zero-fills to round_up(len,128).
// ---------------------------------------------------------------------------
__global__ __launch_bounds__(256)
void softmax_dropout_kernel(float* __restrict__ S)
{
    const int i = blockIdx.x;
    const int t = threadIdx.x;
    const int len = i + 1;
    const int wlimit = (len + 127) & ~127;
    float* row = S + (size_t)i * NT;

    const int warp = t >> 5, lane = t & 31;
    __shared__ float red_m[8], red_s[8];

    const float inv_scale = 0.03125f;  // 1/sqrt(1024)

    float vals[16];
    float lm = -INFINITY;
#pragma unroll
    for (int c = 0; c < 16; c++) {
        const int j = t + 256 * c;
        float x = (j < len) ? row[j] * inv_scale : -INFINITY;
        vals[c] = x;
        lm = fmaxf(lm, x);
    }
#pragma unroll
    for (int o = 16; o; o >>= 1) lm = fmaxf(lm, __shfl_xor_sync(~0u, lm, o));
    if (lane == 0) red_m[warp] = lm;
    __syncthreads();
    float m = red_m[0];
#pragma unroll
    for (int w = 1; w < 8; w++) m = fmaxf(m, red_m[w]);

    float ls = 0.f;
#pragma unroll
    for (int c = 0; c < 16; c++) {
        const int j = t + 256 * c;
        if (j < len) {
            float e = __expf(vals[c] - m);
            vals[c] = e;
            ls += e;
        }
    }
#pragma unroll
    for (int o = 16; o; o >>= 1) ls += __shfl_xor_sync(~0u, ls, o);
    if (lane == 0) red_s[warp] = ls;
    __syncthreads();
    float s = 0.f;
#pragma unroll
    for (int w = 0; w < 8; w++) s += red_s[w];

    const float keep_scale = (1.0f / 0.9f) / s;
    const uint32_t base = (uint32_t)i * (uint32_t)NT;
#pragma unroll
    for (int c = 0; c < 16; c++) {
        const int j = t + 256 * c;
        if (j < wlimit) {
            float w = 0.f;
            if (j < len) {
                float u = jax_uniform(base + (uint32_t)j);
                w = (u < 0.9f) ? f2tf32f(vals[c] * keep_scale) : 0.f;
            }
            row[j] = w;
        }
    }
}

// ---------------------------------------------------------------------------
extern "C" void kernel_launch(void* const* d_in, const int* in_sizes, int n_in,
                              void* d_out, int out_size)
{
    const float* x  = (const float*)d_in[0];
    const float* wq = (const float*)d_in[1];
    const float* wk = (const float*)d_in[2];
    const float* wv = (const float*)d_in[3];
    float* out = (float*)d_out;

    float *q, *k, *v, *s, *xr, *wqr, *wkr, *wvr;
    cudaGetSymbolAddress((void**)&q, g_q);
    cudaGetSymbolAddress((void**)&k, g_k);
    cudaGetSymbolAddress((void**)&v, g_v);
    cudaGetSymbolAddress((void**)&s, g_s);
    cudaGetSymbolAddress((void**)&xr, g_xr);
    cudaGetSymbolAddress((void**)&wqr, g_wqr);
    cudaGetSymbolAddress((void**)&wkr, g_wkr);
    cudaGetSymbolAddress((void**)&wvr, g_wvr);

    constexpr int sh_nt = 4 * (128 * 36 + 256 * 36) * 4;       // 221184 B
    constexpr int sh_nn = 3 * (128 * 36 + 32 * 136) * 4;       // 107520 B
    static bool attr_done = false;
    if (!attr_done) {
        cudaFuncSetAttribute(mma_nt_kernel<false, true>,
                             cudaFuncAttributeMaxDynamicSharedMemorySize, sh_nt);
        cudaFuncSetAttribute(mma_nt_kernel<true, false>,
                             cudaFuncAttributeMaxDynamicSharedMemorySize, sh_nt);
        cudaFuncSetAttribute(mma_nn_causal_kernel,
                             cudaFuncAttributeMaxDynamicSharedMemorySize, sh_nn);
        attr_done = true;
    }

    dim3 blk(256);

    // pre-round x and weights to tf32
    round_kernel<<<(NT * DM / 4 + 255) / 256, blk>>>((const float4*)x,  (float4*)xr,  NT * DM / 4);
    round_kernel<<<(DM * DM / 4 + 255) / 256, blk>>>((const float4*)wq, (float4*)wqr, DM * DM / 4);
    round_kernel<<<(DM * DM / 4 + 255) / 256, blk>>>((const float4*)wk, (float4*)wkr, DM * DM / 4);
    round_kernel<<<(DM * DM / 4 + 255) / 256, blk>>>((const float4*)wv, (float4*)wvr, DM * DM / 4);

    // QKV projections fused into one launch via grid.z (outputs tf32-rounded)
    dim3 grid_qkv(DM / 256, NT / 128, 3);
    mma_nt_kernel<false, true><<<grid_qkv, blk, sh_nt>>>(
        xr, wqr, wkr, wvr, q, k, v, NT, DM, DM);

    // scores = Q @ K^T (keep block iff 2*bx <= by; f32 output for softmax)
    dim3 grid_s(NT / 256, NT / 128, 1);
    mma_nt_kernel<true, false><<<grid_s, blk, sh_nt>>>(
        q, k, k, k, s, s, s, NT, NT, DM);

    // softmax + dropout (writes tf32-rounded weights, zero-fills to tile edge)
    softmax_dropout_kernel<<<NT, blk>>>(s);

    // out = weights @ V (causal k-limit per row tile)
    dim3 grid_o(DM / 128, NT / 128);
    mma_nn_causal_kernel<<<grid_o, blk, sh_nn>>>(s, v, out, NT, DM, NT);
}